// round 10
// baseline (speedup 1.0000x reference)
#include <cuda_runtime.h>
#include <cuda_bf16.h>
#include <math.h>

#define SEQL   2048
#define BATCH  2
#define DMODEL 1024
#define NHEADS 16
#define DHEAD  64
#define MR     (BATCH * SEQL)   // 4096 rows
#define NSEG   16
#define SEGROWS (SEQL / NSEG)   // 128
#define KP     (DMODEL / 2)     // 512 bf16-pair columns

// ---------------- scratch ----------------
__device__ float    g_Q[(size_t)MR * DMODEL];          // f32 (LN'd) — head0 input
__device__ float    g_K[(size_t)MR * DMODEL];
__device__ float    g_V[(size_t)MR * DMODEL];
__device__ float    g_Xr[(size_t)MR * DMODEL];         // tf32-ROUNDED f32 copies (x1 path)
__device__ float    g_Wr[(size_t)2 * DMODEL * DMODEL]; // Wq then Wk, rounded
__device__ unsigned g_Qt[(size_t)MR * DMODEL];         // tf32 hi bits, PRE-SCALED by 0.125
__device__ unsigned g_Kt[(size_t)MR * DMODEL];         // tf32 hi bits (unscaled)
__device__ unsigned g_Xh[(size_t)MR * KP];             // bf16 pair splits
__device__ unsigned g_Xl[(size_t)MR * KP];
__device__ unsigned g_Wvh[(size_t)DMODEL * KP];
__device__ unsigned g_Wvl[(size_t)DMODEL * KP];
__device__ unsigned g_Woh[(size_t)DMODEL * KP];
__device__ unsigned g_Wol[(size_t)DMODEL * KP];
__device__ unsigned g_Vth[(size_t)BATCH * NHEADS * DHEAD * (SEQL / 2)];
__device__ unsigned g_Vtl[(size_t)BATCH * NHEADS * DHEAD * (SEQL / 2)];
__device__ unsigned g_Oh[(size_t)MR * KP];
__device__ unsigned g_Ol[(size_t)MR * KP];
__device__ float    g_F[(size_t)BATCH * SEQL * SEQL];
__device__ float    g_P[(size_t)BATCH * NSEG * SEQL];

// ---------------- helpers ----------------
__device__ __forceinline__ unsigned f2t(float x) {
    unsigned r;
    asm("cvt.rna.tf32.f32 %0, %1;" : "=r"(r) : "f"(x));
    return r;
}

__device__ __forceinline__ void bsplit(float x0, float x1, unsigned& h, unsigned& l) {
    asm("cvt.rn.bf16x2.f32 %0, %1, %2;" : "=r"(h) : "f"(x1), "f"(x0));
    __nv_bfloat162 hb = *reinterpret_cast<__nv_bfloat162*>(&h);
    float2 hf = __bfloat1622float2(hb);
    float r0 = x0 - hf.x, r1 = x1 - hf.y;
    asm("cvt.rn.bf16x2.f32 %0, %1, %2;" : "=r"(l) : "f"(r1), "f"(r0));
}

__device__ __forceinline__ void cpa16(void* smem, const void* gmem) {
    unsigned s = (unsigned)__cvta_generic_to_shared(smem);
    asm volatile("cp.async.cg.shared.global [%0], [%1], 16;" :: "r"(s), "l"(gmem));
}
#define CP_COMMIT() asm volatile("cp.async.commit_group;")
#define CP_WAIT1()  asm volatile("cp.async.wait_group 1;")
#define CP_WAIT0()  asm volatile("cp.async.wait_group 0;")

#define MMA(C, A0, A1, A2, A3, B0, B1)                                         \
    asm volatile(                                                              \
        "mma.sync.aligned.m16n8k8.row.col.f32.tf32.tf32.f32 "                  \
        "{%0,%1,%2,%3},{%4,%5,%6,%7},{%8,%9},{%0,%1,%2,%3};"                   \
        : "+f"((C)[0]), "+f"((C)[1]), "+f"((C)[2]), "+f"((C)[3])               \
        : "r"(A0), "r"(A1), "r"(A2), "r"(A3), "r"(B0), "r"(B1))

#define MMAB(C, A0, A1, A2, A3, B0, B1)                                        \
    asm volatile(                                                              \
        "mma.sync.aligned.m16n8k16.row.col.f32.bf16.bf16.f32 "                 \
        "{%0,%1,%2,%3},{%4,%5,%6,%7},{%8,%9},{%0,%1,%2,%3};"                   \
        : "+f"((C)[0]), "+f"((C)[1]), "+f"((C)[2]), "+f"((C)[3])               \
        : "r"(A0), "r"(A1), "r"(A2), "r"(A3), "r"(B0), "r"(B1))

// ---------------- elementwise kernels ----------------
__global__ __launch_bounds__(256) void split_pairs(const float* __restrict__ src,
                                                   unsigned* __restrict__ h,
                                                   unsigned* __restrict__ l, int npairs) {
    int i = blockIdx.x * 256 + threadIdx.x;
    if (i < npairs) {
        float2 v = ((const float2*)src)[i];
        unsigned hh, ll;
        bsplit(v.x, v.y, hh, ll);
        h[i] = hh;
        l[i] = ll;
    }
}

// tf32-round (RNA) an f32 stream in place-copy: raw bits of the result feed
// tf32 MMAs with exact round-to-nearest behavior, zero mainloop CVTs.
__global__ __launch_bounds__(256) void round_t(const float* __restrict__ src,
                                               float* __restrict__ dst, int n4) {
    int i = blockIdx.x * 256 + threadIdx.x;
    if (i < n4) {
        float4 v = ((const float4*)src)[i];
        float4 o;
        o.x = __uint_as_float(f2t(v.x));
        o.y = __uint_as_float(f2t(v.y));
        o.z = __uint_as_float(f2t(v.z));
        o.w = __uint_as_float(f2t(v.w));
        ((float4*)dst)[i] = o;
    }
}

// ---------------- mixed-split fused Q/K projection ----------------
// SPLIT=3: head0 tiles, full hi/lo decomposition from ORIGINAL operands.
// SPLIT=1: raw-bit feed of PRE-ROUNDED operands (== tf32 RNA, zero CVTs).
template <int SPLIT>
__device__ __forceinline__ void qk_body(const float* __restrict__ Asrc,
                                        const float* __restrict__ Bsrc,
                                        float* __restrict__ Y,
                                        int m0, int col0,
                                        float (&As)[2][128][20],
                                        float (&Bs)[2][128][20]) {
    const int tid = threadIdx.x, lane = tid & 31, warp = tid >> 5;
    const int g = lane >> 2, tg = lane & 3;
    const int wm = warp >> 2, wn = warp & 3;
    const int lr = tid >> 2, lc = (tid & 3) * 4;

    float c[4][4][4] = {};

#pragma unroll
    for (int t = 0; t < 2; t++) {
        int r = lr + t * 64;
        cpa16(&As[0][r][lc], &Asrc[(size_t)r * DMODEL + lc]);
        cpa16(&Bs[0][r][lc], &Bsrc[(size_t)r * DMODEL + lc]);
    }
    CP_COMMIT();

    const int nIt = DMODEL / 16;
    for (int it = 0; it < nIt; it++) {
        const int st = it & 1;
        if (it + 1 < nIt) {
            const int k0 = (it + 1) * 16;
#pragma unroll
            for (int t = 0; t < 2; t++) {
                int r = lr + t * 64;
                cpa16(&As[st ^ 1][r][lc], &Asrc[(size_t)r * DMODEL + k0 + lc]);
                cpa16(&Bs[st ^ 1][r][lc], &Bsrc[(size_t)r * DMODEL + k0 + lc]);
            }
            CP_COMMIT();
            CP_WAIT1();
        } else {
            CP_WAIT0();
        }
        __syncthreads();

#pragma unroll
        for (int kc = 0; kc < 2; kc++) {
            unsigned bh[4][2], bl[4][2];
#pragma unroll
            for (int ni = 0; ni < 4; ni++) {
                int nb = wn * 32 + ni * 8;
                float b0 = Bs[st][nb + g][kc * 8 + tg];
                float b1 = Bs[st][nb + g][kc * 8 + tg + 4];
                if (SPLIT == 3) {
                    bh[ni][0] = f2t(b0);
                    bh[ni][1] = f2t(b1);
                    bl[ni][0] = f2t(b0 - __uint_as_float(bh[ni][0]));
                    bl[ni][1] = f2t(b1 - __uint_as_float(bh[ni][1]));
                } else {
                    bh[ni][0] = __float_as_uint(b0);   // pre-rounded: exact RNA tf32
                    bh[ni][1] = __float_as_uint(b1);
                }
            }
#pragma unroll
            for (int mi = 0; mi < 4; mi++) {
                int rm = wm * 64 + mi * 16;
                float a0 = As[st][rm + g][kc * 8 + tg];
                float a1 = As[st][rm + g + 8][kc * 8 + tg];
                float a2 = As[st][rm + g][kc * 8 + tg + 4];
                float a3 = As[st][rm + g + 8][kc * 8 + tg + 4];
                unsigned ah0, ah1, ah2, ah3;
                unsigned al0 = 0, al1 = 0, al2 = 0, al3 = 0;
                if (SPLIT == 3) {
                    ah0 = f2t(a0); ah1 = f2t(a1); ah2 = f2t(a2); ah3 = f2t(a3);
                    al0 = f2t(a0 - __uint_as_float(ah0));
                    al1 = f2t(a1 - __uint_as_float(ah1));
                    al2 = f2t(a2 - __uint_as_float(ah2));
                    al3 = f2t(a3 - __uint_as_float(ah3));
                } else {
                    ah0 = __float_as_uint(a0); ah1 = __float_as_uint(a1);
                    ah2 = __float_as_uint(a2); ah3 = __float_as_uint(a3);
                }
#pragma unroll
                for (int ni = 0; ni < 4; ni++) {
                    MMA(c[mi][ni], ah0, ah1, ah2, ah3, bh[ni][0], bh[ni][1]);
                    if (SPLIT == 3) {
                        MMA(c[mi][ni], ah0, ah1, ah2, ah3, bl[ni][0], bl[ni][1]);
                        MMA(c[mi][ni], al0, al1, al2, al3, bh[ni][0], bh[ni][1]);
                    }
                }
            }
        }
        __syncthreads();
    }

#pragma unroll
    for (int mi = 0; mi < 4; mi++)
#pragma unroll
        for (int ni = 0; ni < 4; ni++) {
            int r = m0 + wm * 64 + mi * 16 + g;
            int col = col0 + wn * 32 + ni * 8 + 2 * tg;
            *(float2*)&Y[(size_t)r * DMODEL + col] = make_float2(c[mi][ni][0], c[mi][ni][1]);
            *(float2*)&Y[(size_t)(r + 8) * DMODEL + col] = make_float2(c[mi][ni][2], c[mi][ni][3]);
        }
}

__global__ __launch_bounds__(256) void gemm_qk(const float* __restrict__ X,
                                               const float* __restrict__ Wq,
                                               const float* __restrict__ Wk,
                                               const float* __restrict__ Xr,
                                               const float* __restrict__ Wr,
                                               float* __restrict__ Q,
                                               float* __restrict__ K) {
    __shared__ float As[2][128][20];
    __shared__ float Bs[2][128][20];
    const int ntile = blockIdx.x;                 // 0..7 Q cols, 8..15 K cols
    const int m0 = blockIdx.y * 128;
    float* Y = (ntile < 8) ? Q : K;
    const int col0 = (ntile & 7) * 128;

    if (ntile == 0 || ntile == 8) {
        const float* Asrc = X + (size_t)m0 * DMODEL;
        const float* Bsrc = (ntile < 8) ? Wq : Wk;
        qk_body<3>(Asrc, Bsrc, Y, m0, col0, As, Bs);   // head0 columns: fp32-class
    } else {
        const float* Asrc = Xr + (size_t)m0 * DMODEL;
        const float* Bsrc = Wr + (size_t)ntile * 128 * DMODEL;  // Wq rows then Wk rows
        qk_body<1>(Asrc, Bsrc, Y, m0, col0, As, Bs);   // attention-only heads: tf32x1 RNA
    }
}

// ---------------- GEMM bf16 x3, cp.async double-buffered ----------
__global__ __launch_bounds__(256) void gemm_bf3(const unsigned* __restrict__ Ah,
                                                const unsigned* __restrict__ Al,
                                                const unsigned* __restrict__ Bh,
                                                const unsigned* __restrict__ Bl,
                                                float* __restrict__ Y,
                                                int M, int N, int Kp) {
    extern __shared__ unsigned dsm[];
    const int AS = 128 * 20;
    const int tid = threadIdx.x, lane = tid & 31, warp = tid >> 5;
    const int g = lane >> 2, tg = lane & 3;
    const int wm = warp >> 2, wn = warp & 3;
    const int m0 = blockIdx.y * 128, n0 = blockIdx.x * 128;

    const int lr = tid >> 2, lc = (tid & 3) * 4;

    float c[4][4][4] = {};

    {
        unsigned* base = dsm;
#pragma unroll
        for (int t = 0; t < 2; t++) {
            int r = lr + t * 64;
            cpa16(&base[0 * AS + r * 20 + lc], &Ah[(size_t)(m0 + r) * Kp + lc]);
            cpa16(&base[1 * AS + r * 20 + lc], &Al[(size_t)(m0 + r) * Kp + lc]);
            cpa16(&base[2 * AS + r * 20 + lc], &Bh[(size_t)(n0 + r) * Kp + lc]);
            cpa16(&base[3 * AS + r * 20 + lc], &Bl[(size_t)(n0 + r) * Kp + lc]);
        }
        CP_COMMIT();
    }

    const int nIt = Kp / 16;
    for (int it = 0; it < nIt; it++) {
        const int st = it & 1;
        if (it + 1 < nIt) {
            const int k0 = (it + 1) * 16;
            unsigned* base = dsm + (st ^ 1) * 4 * AS;
#pragma unroll
            for (int t = 0; t < 2; t++) {
                int r = lr + t * 64;
                cpa16(&base[0 * AS + r * 20 + lc], &Ah[(size_t)(m0 + r) * Kp + k0 + lc]);
                cpa16(&base[1 * AS + r * 20 + lc], &Al[(size_t)(m0 + r) * Kp + k0 + lc]);
                cpa16(&base[2 * AS + r * 20 + lc], &Bh[(size_t)(n0 + r) * Kp + k0 + lc]);
                cpa16(&base[3 * AS + r * 20 + lc], &Bl[(size_t)(n0 + r) * Kp + k0 + lc]);
            }
            CP_COMMIT();
            CP_WAIT1();
        } else {
            CP_WAIT0();
        }
        __syncthreads();

        unsigned* sAh = dsm + st * 4 * AS;
        unsigned* sAl = sAh + AS;
        unsigned* sBh = sAh + 2 * AS;
        unsigned* sBl = sAh + 3 * AS;
#pragma unroll
        for (int kc = 0; kc < 2; kc++) {
            unsigned bhf[4][2], blf[4][2];
#pragma unroll
            for (int ni = 0; ni < 4; ni++) {
                int nb = (wn * 32 + ni * 8 + g) * 20 + kc * 8 + tg;
                bhf[ni][0] = sBh[nb];
                bhf[ni][1] = sBh[nb + 4];
                blf[ni][0] = sBl[nb];
                blf[ni][1] = sBl[nb + 4];
            }
#pragma unroll
            for (int mi = 0; mi < 4; mi++) {
                int r1 = (wm * 64 + mi * 16 + g) * 20 + kc * 8 + tg;
                int r2 = r1 + 8 * 20;
                unsigned ah0 = sAh[r1], ah1 = sAh[r2], ah2 = sAh[r1 + 4], ah3 = sAh[r2 + 4];
                unsigned al0 = sAl[r1], al1 = sAl[r2], al2 = sAl[r1 + 4], al3 = sAl[r2 + 4];
#pragma unroll
                for (int ni = 0; ni < 4; ni++) {
                    MMAB(c[mi][ni], ah0, ah1, ah2, ah3, bhf[ni][0], bhf[ni][1]);
                    MMAB(c[mi][ni], ah0, ah1, ah2, ah3, blf[ni][0], blf[ni][1]);
                    MMAB(c[mi][ni], al0, al1, al2, al3, bhf[ni][0], bhf[ni][1]);
                }
            }
        }
        __syncthreads();
    }

#pragma unroll
    for (int mi = 0; mi < 4; mi++)
#pragma unroll
        for (int ni = 0; ni < 4; ni++) {
            int r = m0 + wm * 64 + mi * 16 + g;
            int col = n0 + wn * 32 + ni * 8 + 2 * tg;
            *(float2*)&Y[(size_t)r * N + col] = make_float2(c[mi][ni][0], c[mi][ni][1]);
            *(float2*)&Y[(size_t)(r + 8) * N + col] = make_float2(c[mi][ni][2], c[mi][ni][3]);
        }
}

// ---------------- row LayerNorm (in place) + scaled tf32-truncated copy ----------------
__global__ __launch_bounds__(256) void ln_rows_t(float* __restrict__ Y,
                                                 const float* __restrict__ g,
                                                 const float* __restrict__ b,
                                                 unsigned* __restrict__ T,
                                                 float scale) {
    const int row = blockIdx.x;
    float* y = Y + (size_t)row * DMODEL;
    unsigned* t = T + (size_t)row * DMODEL;
    __shared__ float red[256];

    float s = 0.f;
    for (int i = threadIdx.x; i < DMODEL; i += 256) s += y[i];
    red[threadIdx.x] = s;
    __syncthreads();
    for (int o = 128; o > 0; o >>= 1) {
        if (threadIdx.x < o) red[threadIdx.x] += red[threadIdx.x + o];
        __syncthreads();
    }
    const float mu = red[0] * (1.0f / DMODEL);
    __syncthreads();

    float v = 0.f;
    for (int i = threadIdx.x; i < DMODEL; i += 256) {
        float d = y[i] - mu;
        v += d * d;
    }
    red[threadIdx.x] = v;
    __syncthreads();
    for (int o = 128; o > 0; o >>= 1) {
        if (threadIdx.x < o) red[threadIdx.x] += red[threadIdx.x + o];
        __syncthreads();
    }
    const float rstd = rsqrtf(red[0] * (1.0f / DMODEL) + 1e-5f);
    __syncthreads();

    for (int i = threadIdx.x; i < DMODEL; i += 256) {
        float val = (y[i] - mu) * rstd * g[i] + b[i];
        y[i] = val;
        t[i] = f2t(val * scale);
    }
}

// ---------------- V transpose + bf16 split ----------------
__global__ __launch_bounds__(256) void vt_split() {
    __shared__ float tile[64][68];
    const int b = blockIdx.z, h = blockIdx.y, n0 = blockIdx.x * 64;
    const int tid = threadIdx.x;
#pragma unroll
    for (int t = 0; t < 4; t++) {
        int idx = tid + t * 256;
        int r = idx >> 4, c4 = (idx & 15) * 4;
        *(float4*)&tile[r][c4] =
            *(const float4*)&g_V[(size_t)(b * SEQL + n0 + r) * DMODEL + h * DHEAD + c4];
    }
    __syncthreads();
#pragma unroll
    for (int t = 0; t < 8; t++) {
        int idx = tid + t * 256;
        int d = idx >> 5, j = idx & 31;
        unsigned hh, ll;
        bsplit(tile[2 * j][d], tile[2 * j + 1][d], hh, ll);
        size_t off = ((size_t)((b * NHEADS + h) * DHEAD + d)) * (SEQL / 2) + (n0 >> 1) + j;
        g_Vth[off] = hh;
        g_Vtl[off] = ll;
    }
}

// ---------------- head-0 scores via tf32 x3 (upper-tri early exit) ----------------
__global__ __launch_bounds__(256) void head0_tc() {
    const int tid = threadIdx.x, lane = tid & 31, warp = tid >> 5;
    const int g = lane >> 2, tg = lane & 3;
    const int wm = warp >> 2, wn = warp & 3;
    const int bb = blockIdx.z;
    const int r0 = blockIdx.y * 128, mm0 = blockIdx.x * 128;

    if (mm0 >= r0 + 128) {
        const float2 z = make_float2(0.f, 0.f);
#pragma unroll
        for (int mi = 0; mi < 4; mi++)
#pragma unroll
            for (int ni = 0; ni < 4; ni++) {
                int r1 = r0 + wm * 64 + mi * 16 + g;
                int m = mm0 + wn * 32 + ni * 8 + 2 * tg;
                *(float2*)&g_F[(size_t)(bb * SEQL + r1) * SEQL + m] = z;
                *(float2*)&g_F[(size_t)(bb * SEQL + r1 + 8) * SEQL + m] = z;
            }
        return;
    }

    __shared__ float As[128][36];
    __shared__ float Bs[128][36];
    const float* Aq = g_Q + (size_t)(bb * SEQL + r0) * DMODEL;
    const float* Bk = g_K + (size_t)(bb * SEQL + mm0) * DMODEL;
    const int lrow = tid >> 3, lcol = (tid & 7) * 4;

    float c[4][4][4] = {};

    for (int k0 = 0; k0 < 64; k0 += 32) {
#pragma unroll
        for (int it = 0; it < 4; it++) {
            int r = lrow + it * 32;
            *(float4*)&As[r][lcol] = *(const float4*)&Aq[(size_t)r * DMODEL + k0 + lcol];
            *(float4*)&Bs[r][lcol] = *(const float4*)&Bk[(size_t)r * DMODEL + k0 + lcol];
        }
        __syncthreads();
#pragma unroll
        for (int kc = 0; kc < 4; kc++) {
            unsigned bh[4][2], bl[4][2];
#pragma unroll
            for (int ni = 0; ni < 4; ni++) {
                int nb = wn * 32 + ni * 8;
                float b0 = Bs[nb + g][kc * 8 + tg];
                float b1 = Bs[nb + g][kc * 8 + tg + 4];
                bh[ni][0] = f2t(b0);
                bh[ni][1] = f2t(b1);
                bl[ni][0] = f2t(b0 - __uint_as_float(bh[ni][0]));
                bl[ni][1] = f2t(b1 - __uint_as_float(bh[ni][1]));
            }
#pragma unroll
            for (int mi = 0; mi < 4; mi++) {
                int rm = wm * 64 + mi * 16;
                float a0 = As[rm + g][kc * 8 + tg];
                float a1 = As[rm + g + 8][kc * 8 + tg];
                float a2 = As[rm + g][kc * 8 + tg + 4];
                float a3 = As[rm + g + 8][kc * 8 + tg + 4];
                unsigned ah0 = f2t(a0), ah1 = f2t(a1), ah2 = f2t(a2), ah3 = f2t(a3);
                unsigned al0 = f2t(a0 - __uint_as_float(ah0));
                unsigned al1 = f2t(a1 - __uint_as_float(ah1));
                unsigned al2 = f2t(a2 - __uint_as_float(ah2));
                unsigned al3 = f2t(a3 - __uint_as_float(ah3));
#pragma unroll
                for (int ni = 0; ni < 4; ni++) {
                    MMA(c[mi][ni], ah0, ah1, ah2, ah3, bh[ni][0], bh[ni][1]);
                    MMA(c[mi][ni], ah0, ah1, ah2, ah3, bl[ni][0], bl[ni][1]);
                    MMA(c[mi][ni], al0, al1, al2, al3, bh[ni][0], bh[ni][1]);
                }
            }
        }
        __syncthreads();
    }

#pragma unroll
    for (int mi = 0; mi < 4; mi++)
#pragma unroll
        for (int ni = 0; ni < 4; ni++) {
            int r1 = r0 + wm * 64 + mi * 16 + g;
            int r2 = r1 + 8;
            int m = mm0 + wn * 32 + ni * 8 + 2 * tg;
            float v0 = c[mi][ni][0] * 0.125f;
            float v1 = c[mi][ni][1] * 0.125f;
            float v2 = c[mi][ni][2] * 0.125f;
            float v3 = c[mi][ni][3] * 0.125f;
            v0 = (m >= 1 && m < r1) ? fmaxf(v0, 0.f) : 0.f;
            v1 = (m + 1 < r1) ? fmaxf(v1, 0.f) : 0.f;
            v2 = (m >= 1 && m < r2) ? fmaxf(v2, 0.f) : 0.f;
            v3 = (m + 1 < r2) ? fmaxf(v3, 0.f) : 0.f;
            *(float2*)&g_F[(size_t)(bb * SEQL + r1) * SEQL + m] = make_float2(v0, v1);
            *(float2*)&g_F[(size_t)(bb * SEQL + r2) * SEQL + m] = make_float2(v2, v3);
        }
}

// ---------------- 3-pass exclusive column scan ----------------
__global__ __launch_bounds__(256) void seg_sum() {
    const int m = blockIdx.x * 256 + threadIdx.x;
    const int seg = blockIdx.y, b = blockIdx.z;
    const float* base = g_F + (size_t)(b * SEQL + seg * SEGROWS) * SEQL + m;
    float s = 0.f;
#pragma unroll 4
    for (int r = 0; r < SEGROWS; r++) s += base[(size_t)r * SEQL];
    g_P[(size_t)(b * NSEG + seg) * SEQL + m] = s;
}

__global__ __launch_bounds__(256) void seg_scan() {
    const int m = blockIdx.x * 256 + threadIdx.x;
    const int b = blockIdx.y;
    float acc = 0.f;
#pragma unroll
    for (int s = 0; s < NSEG; s++) {
        size_t idx = (size_t)(b * NSEG + s) * SEQL + m;
        float v = g_P[idx];
        g_P[idx] = acc;
        acc += v;
    }
}

__global__ __launch_bounds__(256) void final_scan() {
    const int m = blockIdx.x * 256 + threadIdx.x;
    const int seg = blockIdx.y, b = blockIdx.z;
    float acc = g_P[(size_t)(b * NSEG + seg) * SEQL + m];
    float* base = g_F + (size_t)(b * SEQL + seg * SEGROWS) * SEQL + m;
#pragma unroll 4
    for (int r = 0; r < SEGROWS; r++) {
        float c = base[(size_t)r * SEQL];
        base[(size_t)r * SEQL] = acc;
        acc += c;
    }
}

// ---------------- flash attention: BM=128 (8 warps), 64-key tiles ----------
// QK tf32x1 (pre-scaled Qt), PV bf16x3, cp.async double-buffered K/V.
#define ATTN_KSZ  (64 * 68)
#define ATTN_VSZ  (64 * 36)
#define ATTN_VHOFF (2 * ATTN_KSZ)
#define ATTN_VLOFF (2 * ATTN_KSZ + 2 * ATTN_VSZ)
#define ATTN_SMEM  ((2 * ATTN_KSZ + 4 * ATTN_VSZ) * 4)

__global__ __launch_bounds__(256) void attn_bf() {
    extern __shared__ unsigned sm[];
    const int b = blockIdx.z, h = blockIdx.y;
    const int qt = (int)gridDim.x - 1 - (int)blockIdx.x;  // longest first
    const int q0 = qt * 128;
    const int tid = threadIdx.x, lane = tid & 31, w = tid >> 5;
    const int g = lane >> 2, tg = lane & 3;

    const int R1 = q0 + w * 16 + g;     // this warp's global rows
    const int R2 = R1 + 8;

    unsigned qa[8][4];
    const size_t qr1 = (size_t)(b * SEQL + R1) * DMODEL + h * DHEAD;
    const size_t qr2 = qr1 + 8 * DMODEL;
#pragma unroll
    for (int kc = 0; kc < 8; kc++) {
        qa[kc][0] = g_Qt[qr1 + kc * 8 + tg];
        qa[kc][1] = g_Qt[qr2 + kc * 8 + tg];
        qa[kc][2] = g_Qt[qr1 + kc * 8 + tg + 4];
        qa[kc][3] = g_Qt[qr2 + kc * 8 + tg + 4];
    }

    float o[8][4] = {};
    float qm0 = -1e30f, qm1 = -1e30f, lsum0 = 0.f, lsum1 = 0.f;

    const int nkt = 2 * qt + 2;   // key tiles covering [0, q0+128)

    // prefetch tile 0
    {
        const size_t kbase = (size_t)(b * SEQL) * DMODEL + h * DHEAD;
        const size_t vbase = (size_t)((b * NHEADS + h) * DHEAD) * (SEQL / 2);
#pragma unroll
        for (int t = 0; t < 4; t++) {
            int idx = tid + t * 256;
            int r = idx >> 4, c4 = (idx & 15) * 4;
            cpa16(&sm[r * 68 + c4], &g_Kt[kbase + (size_t)r * DMODEL + c4]);
        }
#pragma unroll
        for (int t = 0; t < 2; t++) {
            int idx = tid + t * 256;
            int r = idx >> 3, c4 = (idx & 7) * 4;
            cpa16(&sm[ATTN_VHOFF + r * 36 + c4], &g_Vth[vbase + (size_t)r * (SEQL / 2) + c4]);
            cpa16(&sm[ATTN_VLOFF + r * 36 + c4], &g_Vtl[vbase + (size_t)r * (SEQL / 2) + c4]);
        }
        CP_COMMIT();
    }

    for (int kt = 0; kt < nkt; kt++) {
        const int buf = kt & 1;
        const int m0 = kt * 64;
        if (kt + 1 < nkt) {
            const int m0n = m0 + 64;
            const int nb = buf ^ 1;
            const size_t kbase = (size_t)(b * SEQL + m0n) * DMODEL + h * DHEAD;
            const size_t vbase = (size_t)((b * NHEADS + h) * DHEAD) * (SEQL / 2) + (m0n >> 1);
#pragma unroll
            for (int t = 0; t < 4; t++) {
                int idx = tid + t * 256;
                int r = idx >> 4, c4 = (idx & 15) * 4;
                cpa16(&sm[nb * ATTN_KSZ + r * 68 + c4], &g_Kt[kbase + (size_t)r * DMODEL + c4]);
            }
#pragma unroll
            for (int t = 0; t < 2; t++) {
                int idx = tid + t * 256;
                int r = idx >> 3, c4 = (idx & 7) * 4;
                cpa16(&sm[ATTN_VHOFF + nb * ATTN_VSZ + r * 36 + c4],
                      &g_Vth[vbase + (size_t)r * (SEQL / 2) + c4]);
                cpa16(&sm[ATTN_VLOFF + nb * ATTN_VSZ + r * 36 + c4],
                      &g_Vtl[vbase + (size_t)r * (SEQL / 2) + c4]);
            }
            CP_COMMIT();
            CP_WAIT1();
        } else {
            CP_WAIT0();
        }
        __syncthreads();

        const unsigned* sKt = sm + buf * ATTN_KSZ;
        const unsigned* sVh = sm + ATTN_VHOFF + buf * ATTN_VSZ;
        const unsigned* sVl = sm + ATTN_VLOFF + buf * ATTN_VSZ;

        float sc[8][4] = {};
#pragma unroll
        for (int kc = 0; kc < 8; kc++) {
#pragma unroll
            for (int ni = 0; ni < 8; ni++) {
                unsigned b0 = sKt[(ni * 8 + g) * 68 + kc * 8 + tg];
                unsigned b1 = sKt[(ni * 8 + g) * 68 + kc * 8 + tg + 4];
                MMA(sc[ni], qa[kc][0], qa[kc][1], qa[kc][2], qa[kc][3], b0, b1);
            }
        }

        const bool band = (m0 + 63 > q0);   // diagonal band: last two tiles
        const size_t frow1 = (size_t)(b * SEQL + R1) * SEQL + m0;
        const size_t frow2 = (size_t)(b * SEQL + R2) * SEQL + m0;
        float mx0 = -1e30f, mx1 = -1e30f;
#pragma unroll
        for (int ni = 0; ni < 8; ni++) {
            int cl = ni * 8 + 2 * tg;
            int Cg = m0 + cl;                 // global key index
            float2 f1 = *(const float2*)&g_F[frow1 + cl];
            float2 f2 = *(const float2*)&g_F[frow2 + cl];
            float v0 = sc[ni][0] - f1.x;
            float v1 = sc[ni][1] - f1.y;
            float v2 = sc[ni][2] - f2.x;
            float v3 = sc[ni][3] - f2.y;
            if (band) {
                if (Cg > R1) v0 = -1e30f;
                if (Cg + 1 > R1) v1 = -1e30f;
                if (Cg > R2) v2 = -1e30f;
                if (Cg + 1 > R2) v3 = -1e30f;
            }
            sc[ni][0] = v0; sc[ni][1] = v1; sc[ni][2] = v2; sc[ni][3] = v3;
            mx0 = fmaxf(mx0, fmaxf(v0, v1));
            mx1 = fmaxf(mx1, fmaxf(v2, v3));
        }
        mx0 = fmaxf(mx0, __shfl_xor_sync(0xffffffffu, mx0, 1));
        mx0 = fmaxf(mx0, __shfl_xor_sync(0xffffffffu, mx0, 2));
        mx1 = fmaxf(mx1, __shfl_xor_sync(0xffffffffu, mx1, 1));
        mx1 = fmaxf(mx1, __shfl_xor_sync(0xffffffffu, mx1, 2));
        const float nm0 = fmaxf(qm0, mx0), nm1 = fmaxf(qm1, mx1);
        const float s0 = __expf(qm0 - nm0), s1 = __expf(qm1 - nm1);
        float ps0 = 0.f, ps1 = 0.f;
#pragma unroll
        for (int ni = 0; ni < 8; ni++) {
            float e0 = __expf(sc[ni][0] - nm0);
            float e1 = __expf(sc[ni][1] - nm0);
            float e2 = __expf(sc[ni][2] - nm1);
            float e3 = __expf(sc[ni][3] - nm1);
            sc[ni][0] = e0; sc[ni][1] = e1; sc[ni][2] = e2; sc[ni][3] = e3;
            ps0 += e0 + e1;
            ps1 += e2 + e3;
            o[ni][0] *= s0; o[ni][1] *= s0; o[ni][2] *= s1; o[ni][3] *= s1;
        }
        ps0 += __shfl_xor_sync(0xffffffffu, ps0, 1);
        ps0 += __shfl_xor_sync(0xffffffffu, ps0, 2);
        ps1 += __shfl_xor_sync(0xffffffffu, ps1, 1);
        ps1 += __shfl_xor_sync(0xffffffffu, ps1, 2);
        lsum0 = lsum0 * s0 + ps0;
        lsum1 = lsum1 * s1 + ps1;
        qm0 = nm0; qm1 = nm1;

#pragma unroll
        for (int kc2 = 0; kc2 < 4; kc2++) {
            unsigned ph0, pl0, ph1, pl1, ph2, pl2, ph3, pl3;
            bsplit(sc[kc2 * 2][0], sc[kc2 * 2][1], ph0, pl0);
            bsplit(sc[kc2 * 2][2], sc[kc2 * 2][3], ph1, pl1);
            bsplit(sc[kc2 * 2 + 1][0], sc[kc2 * 2 + 1][1], ph2, pl2);
            bsplit(sc[kc2 * 2 + 1][2], sc[kc2 * 2 + 1][3], ph3, pl3);
#pragma unroll
            for (int ni = 0; ni < 8; ni++) {
                int vb = (ni * 8 + g) * 36 + kc2 * 8 + tg;
                unsigned vh0 = sVh[vb], vh1 = sVh[vb + 4];
                unsigned vl0 = sVl[vb], vl1 = sVl[vb + 4];
                MMAB(o[ni], ph0, ph1, ph2, ph3, vh0, vh1);
                MMAB(o[ni], ph0, ph1, ph2, ph3, vl0, vl1);
                MMAB(o[ni], pl0, pl1, pl2, pl3, vh0, vh1);
            }
        }
        __syncthreads();
    }

    const float i0 = 1.0f / lsum0, i1 = 1.0f / lsum1;
    const size_t or1 = (size_t)(b * SEQL + R1) * KP + h * 32;
    const size_t or2 = (size_t)(b * SEQL + R2) * KP + h * 32;
#pragma unroll
    for (int ni = 0; ni < 8; ni++) {
        unsigned hh, ll;
        bsplit(o[ni][0] * i0, o[ni][1] * i0, hh, ll);
        g_Oh[or1 + ni * 4 + tg] = hh;
        g_Ol[or1 + ni * 4 + tg] = ll;
        bsplit(o[ni][2] * i1, o[ni][3] * i1, hh, ll);
        g_Oh[or2 + ni * 4 + tg] = hh;
        g_Ol[or2 + ni * 4 + tg] = ll;
    }
}

// ---------------- launch ----------------
extern "C" void kernel_launch(void* const* d_in, const int* in_sizes, int n_in,
                              void* d_out, int out_size) {
    const float* X  = (const float*)d_in[0];
    const float* Wq = (const float*)d_in[1];
    const float* Wk = (const float*)d_in[2];
    const float* Wv = (const float*)d_in[3];
    const float* Wo = (const float*)d_in[4];
    const float* gq = (const float*)d_in[5];
    const float* bq = (const float*)d_in[6];
    const float* gk = (const float*)d_in[7];
    const float* bk = (const float*)d_in[8];
    float* out = (float*)d_out;

    float *pQ, *pK, *pV, *pXr, *pWr;
    unsigned *pQt, *pKt, *pXh, *pXl, *pWvh, *pWvl, *pWoh, *pWol, *pOh, *pOl;
    cudaGetSymbolAddress((void**)&pQ, g_Q);
    cudaGetSymbolAddress((void**)&pK, g_K);
    cudaGetSymbolAddress((void**)&pV, g_V);
    cudaGetSymbolAddress((void**)&pXr, g_Xr);
    cudaGetSymbolAddress((void**)&pWr, g_Wr);
    cudaGetSymbolAddress((void**)&pQt, g_Qt);
    cudaGetSymbolAddress((void**)&pKt, g_Kt);
    cudaGetSymbolAddress((void**)&pXh, g_Xh);
    cudaGetSymbolAddress((void**)&pXl, g_Xl);
    cudaGetSymbolAddress((void**)&pWvh, g_Wvh);
    cudaGetSymbolAddress((void**)&pWvl, g_Wvl);
    cudaGetSymbolAddress((void**)&pWoh, g_Woh);
    cudaGetSymbolAddress((void**)&pWol, g_Wol);
    cudaGetSymbolAddress((void**)&pOh, g_Oh);
    cudaGetSymbolAddress((void**)&pOl, g_Ol);

    const int NW = DMODEL * DMODEL;
    const int GEMM_SMEM = 2 * 4 * 128 * 20 * 4;   // 81920 bytes
    cudaFuncSetAttribute(gemm_bf3, cudaFuncAttributeMaxDynamicSharedMemorySize, GEMM_SMEM);
    cudaFuncSetAttribute(attn_bf, cudaFuncAttributeMaxDynamicSharedMemorySize, ATTN_SMEM);

    // operand pre-passes
    split_pairs<<<(MR * KP + 255) / 256, 256>>>(X, pXh, pXl, MR * KP);
    split_pairs<<<(NW / 2 + 255) / 256, 256>>>(Wv, pWvh, pWvl, NW / 2);
    split_pairs<<<(NW / 2 + 255) / 256, 256>>>(Wo, pWoh, pWol, NW / 2);
    round_t<<<(MR * DMODEL / 4 + 255) / 256, 256>>>(X, pXr, MR * DMODEL / 4);
    round_t<<<(NW / 4 + 255) / 256, 256>>>(Wq, pWr, NW / 4);
    round_t<<<(NW / 4 + 255) / 256, 256>>>(Wk, pWr + (size_t)NW, NW / 4);

    // fused Q,K projection (mixed tf32 split, RNA everywhere) + V projection (bf16x3)
    gemm_qk<<<dim3(16, MR / 128), 256>>>(X, Wq, Wk, pXr, pWr, pQ, pK);
    gemm_bf3<<<dim3(DMODEL / 128, MR / 128), 256, GEMM_SMEM>>>(pXh, pXl, pWvh, pWvl, pV,
                                                               MR, DMODEL, KP);

    ln_rows_t<<<MR, 256>>>(pQ, gq, bq, pQt, 0.125f);   // Qt pre-scaled for attn logits
    ln_rows_t<<<MR, 256>>>(pK, gk, bk, pKt, 1.0f);
    vt_split<<<dim3(SEQL / 64, NHEADS, BATCH), 256>>>();

    head0_tc<<<dim3(SEQL / 128, SEQL / 128, BATCH), 256>>>();
    seg_sum<<<dim3(SEQL / 256, NSEG, BATCH), 256>>>();
    seg_scan<<<dim3(SEQL / 256, BATCH), 256>>>();
    final_scan<<<dim3(SEQL / 256, NSEG, BATCH), 256>>>();

    attn_bf<<<dim3(SEQL / 128, NHEADS, BATCH), 256, ATTN_SMEM>>>();

    gemm_bf3<<<dim3(DMODEL / 128, MR / 128), 256, GEMM_SMEM>>>(pOh, pOl, pWoh, pWol, out,
                                                               MR, DMODEL, KP);
}

// round 11
// speedup vs baseline: 1.0591x; 1.0591x over previous
#include <cuda_runtime.h>
#include <cuda_bf16.h>
#include <math.h>

#define SEQL   2048
#define BATCH  2
#define DMODEL 1024
#define NHEADS 16
#define DHEAD  64
#define MR     (BATCH * SEQL)   // 4096 rows
#define NSEG   16
#define SEGROWS (SEQL / NSEG)   // 128
#define KP     (DMODEL / 2)     // 512 bf16-pair columns

// ---------------- scratch ----------------
__device__ float    g_Q[(size_t)MR * DMODEL];          // f32 (LN'd) — head0 input
__device__ float    g_K[(size_t)MR * DMODEL];
__device__ float    g_V[(size_t)MR * DMODEL];
__device__ float    g_Xr[(size_t)MR * DMODEL];         // tf32-ROUNDED f32 copies (x1 path)
__device__ float    g_Wr[(size_t)2 * DMODEL * DMODEL]; // Wq then Wk, rounded
__device__ unsigned g_Qt[(size_t)MR * DMODEL];         // tf32 hi bits, PRE-SCALED by 0.125
__device__ unsigned g_Kt[(size_t)MR * DMODEL];         // tf32 hi bits (unscaled)
__device__ unsigned g_Xh[(size_t)MR * KP];             // bf16 pair splits
__device__ unsigned g_Xl[(size_t)MR * KP];
__device__ unsigned g_Wvh[(size_t)DMODEL * KP];
__device__ unsigned g_Wvl[(size_t)DMODEL * KP];
__device__ unsigned g_Woh[(size_t)DMODEL * KP];
__device__ unsigned g_Wol[(size_t)DMODEL * KP];
__device__ unsigned g_Vth[(size_t)BATCH * NHEADS * DHEAD * (SEQL / 2)];
__device__ unsigned g_Vtl[(size_t)BATCH * NHEADS * DHEAD * (SEQL / 2)];
__device__ unsigned g_Oh[(size_t)MR * KP];
__device__ unsigned g_Ol[(size_t)MR * KP];
__device__ float    g_F[(size_t)BATCH * SEQL * SEQL];
__device__ float    g_P[(size_t)BATCH * NSEG * SEQL];

// ---------------- helpers ----------------
__device__ __forceinline__ unsigned f2t(float x) {
    unsigned r;
    asm("cvt.rna.tf32.f32 %0, %1;" : "=r"(r) : "f"(x));
    return r;
}

__device__ __forceinline__ void bsplit(float x0, float x1, unsigned& h, unsigned& l) {
    asm("cvt.rn.bf16x2.f32 %0, %1, %2;" : "=r"(h) : "f"(x1), "f"(x0));
    __nv_bfloat162 hb = *reinterpret_cast<__nv_bfloat162*>(&h);
    float2 hf = __bfloat1622float2(hb);
    float r0 = x0 - hf.x, r1 = x1 - hf.y;
    asm("cvt.rn.bf16x2.f32 %0, %1, %2;" : "=r"(l) : "f"(r1), "f"(r0));
}

__device__ __forceinline__ void cpa16(void* smem, const void* gmem) {
    unsigned s = (unsigned)__cvta_generic_to_shared(smem);
    asm volatile("cp.async.cg.shared.global [%0], [%1], 16;" :: "r"(s), "l"(gmem));
}
#define CP_COMMIT() asm volatile("cp.async.commit_group;")
#define CP_WAIT1()  asm volatile("cp.async.wait_group 1;")
#define CP_WAIT0()  asm volatile("cp.async.wait_group 0;")

#define MMA(C, A0, A1, A2, A3, B0, B1)                                         \
    asm volatile(                                                              \
        "mma.sync.aligned.m16n8k8.row.col.f32.tf32.tf32.f32 "                  \
        "{%0,%1,%2,%3},{%4,%5,%6,%7},{%8,%9},{%0,%1,%2,%3};"                   \
        : "+f"((C)[0]), "+f"((C)[1]), "+f"((C)[2]), "+f"((C)[3])               \
        : "r"(A0), "r"(A1), "r"(A2), "r"(A3), "r"(B0), "r"(B1))

#define MMAB(C, A0, A1, A2, A3, B0, B1)                                        \
    asm volatile(                                                              \
        "mma.sync.aligned.m16n8k16.row.col.f32.bf16.bf16.f32 "                 \
        "{%0,%1,%2,%3},{%4,%5,%6,%7},{%8,%9},{%0,%1,%2,%3};"                   \
        : "+f"((C)[0]), "+f"((C)[1]), "+f"((C)[2]), "+f"((C)[3])               \
        : "r"(A0), "r"(A1), "r"(A2), "r"(A3), "r"(B0), "r"(B1))

// ---------------- elementwise kernels ----------------
// X: produce bf16 hi/lo pairs AND tf32-rounded f32 copy in one read.
__global__ __launch_bounds__(256) void split_pairs_r(const float* __restrict__ src,
                                                     unsigned* __restrict__ h,
                                                     unsigned* __restrict__ l,
                                                     float2* __restrict__ xr, int npairs) {
    int i = blockIdx.x * 256 + threadIdx.x;
    if (i < npairs) {
        float2 v = ((const float2*)src)[i];
        unsigned hh, ll;
        bsplit(v.x, v.y, hh, ll);
        h[i] = hh;
        l[i] = ll;
        float2 o;
        o.x = __uint_as_float(f2t(v.x));
        o.y = __uint_as_float(f2t(v.y));
        xr[i] = o;
    }
}

__global__ __launch_bounds__(256) void split_pairs(const float* __restrict__ src,
                                                   unsigned* __restrict__ h,
                                                   unsigned* __restrict__ l, int npairs) {
    int i = blockIdx.x * 256 + threadIdx.x;
    if (i < npairs) {
        float2 v = ((const float2*)src)[i];
        unsigned hh, ll;
        bsplit(v.x, v.y, hh, ll);
        h[i] = hh;
        l[i] = ll;
    }
}

__global__ __launch_bounds__(256) void round_t(const float* __restrict__ src,
                                               float* __restrict__ dst, int n4) {
    int i = blockIdx.x * 256 + threadIdx.x;
    if (i < n4) {
        float4 v = ((const float4*)src)[i];
        float4 o;
        o.x = __uint_as_float(f2t(v.x));
        o.y = __uint_as_float(f2t(v.y));
        o.z = __uint_as_float(f2t(v.z));
        o.w = __uint_as_float(f2t(v.w));
        ((float4*)dst)[i] = o;
    }
}

// ---------------- mixed-split fused Q/K projection, BK=32 double-buffered ----------
// SPLIT=3: head0 tiles, hi/lo decomposition from ORIGINAL operands.
// SPLIT=1: raw-bit feed of PRE-ROUNDED operands (== tf32 RNA, zero mainloop CVTs).
#define QK_SS   (128 * 36)                   // floats per array per stage
#define QK_SMEM (2 * 2 * QK_SS * 4)          // 73728 bytes

template <int SPLIT>
__device__ __forceinline__ void qk_body(const float* __restrict__ Asrc,
                                        const float* __restrict__ Bsrc,
                                        float* __restrict__ Y,
                                        int m0, int col0,
                                        float* __restrict__ Asm,
                                        float* __restrict__ Bsm) {
    const int tid = threadIdx.x, lane = tid & 31, warp = tid >> 5;
    const int g = lane >> 2, tg = lane & 3;
    const int wm = warp >> 2, wn = warp & 3;

    float c[4][4][4] = {};

    // stage loader: 128 rows x 32 cols per array = 1024 float4; 4 per thread
#define QK_LOAD(stage, k0)                                                     \
    do {                                                                       \
        float* As_ = Asm + (stage) * QK_SS;                                    \
        float* Bs_ = Bsm + (stage) * QK_SS;                                    \
        _Pragma("unroll")                                                      \
        for (int t = 0; t < 4; t++) {                                          \
            int idx = tid + t * 256;                                           \
            int r = idx >> 3, c4 = (idx & 7) * 4;                              \
            cpa16(&As_[r * 36 + c4], &Asrc[(size_t)r * DMODEL + (k0) + c4]);   \
            cpa16(&Bs_[r * 36 + c4], &Bsrc[(size_t)r * DMODEL + (k0) + c4]);   \
        }                                                                      \
    } while (0)

    QK_LOAD(0, 0);
    CP_COMMIT();

    const int nIt = DMODEL / 32;   // 32 stages
    for (int it = 0; it < nIt; it++) {
        const int st = it & 1;
        if (it + 1 < nIt) {
            QK_LOAD(st ^ 1, (it + 1) * 32);
            CP_COMMIT();
            CP_WAIT1();
        } else {
            CP_WAIT0();
        }
        __syncthreads();

        const float* As_ = Asm + st * QK_SS;
        const float* Bs_ = Bsm + st * QK_SS;
#pragma unroll
        for (int kc = 0; kc < 4; kc++) {
            unsigned bh[4][2], bl[4][2];
#pragma unroll
            for (int ni = 0; ni < 4; ni++) {
                int nb = (wn * 32 + ni * 8 + g) * 36 + kc * 8 + tg;
                float b0 = Bs_[nb];
                float b1 = Bs_[nb + 4];
                if (SPLIT == 3) {
                    bh[ni][0] = f2t(b0);
                    bh[ni][1] = f2t(b1);
                    bl[ni][0] = f2t(b0 - __uint_as_float(bh[ni][0]));
                    bl[ni][1] = f2t(b1 - __uint_as_float(bh[ni][1]));
                } else {
                    bh[ni][0] = __float_as_uint(b0);   // pre-rounded: exact RNA tf32
                    bh[ni][1] = __float_as_uint(b1);
                }
            }
#pragma unroll
            for (int mi = 0; mi < 4; mi++) {
                int r1 = (wm * 64 + mi * 16 + g) * 36 + kc * 8 + tg;
                int r2 = r1 + 8 * 36;
                float a0 = As_[r1];
                float a1 = As_[r2];
                float a2 = As_[r1 + 4];
                float a3 = As_[r2 + 4];
                unsigned ah0, ah1, ah2, ah3;
                unsigned al0 = 0, al1 = 0, al2 = 0, al3 = 0;
                if (SPLIT == 3) {
                    ah0 = f2t(a0); ah1 = f2t(a1); ah2 = f2t(a2); ah3 = f2t(a3);
                    al0 = f2t(a0 - __uint_as_float(ah0));
                    al1 = f2t(a1 - __uint_as_float(ah1));
                    al2 = f2t(a2 - __uint_as_float(ah2));
                    al3 = f2t(a3 - __uint_as_float(ah3));
                } else {
                    ah0 = __float_as_uint(a0); ah1 = __float_as_uint(a1);
                    ah2 = __float_as_uint(a2); ah3 = __float_as_uint(a3);
                }
#pragma unroll
                for (int ni = 0; ni < 4; ni++) {
                    MMA(c[mi][ni], ah0, ah1, ah2, ah3, bh[ni][0], bh[ni][1]);
                    if (SPLIT == 3) {
                        MMA(c[mi][ni], ah0, ah1, ah2, ah3, bl[ni][0], bl[ni][1]);
                        MMA(c[mi][ni], al0, al1, al2, al3, bh[ni][0], bh[ni][1]);
                    }
                }
            }
        }
        __syncthreads();
    }
#undef QK_LOAD

#pragma unroll
    for (int mi = 0; mi < 4; mi++)
#pragma unroll
        for (int ni = 0; ni < 4; ni++) {
            int r = m0 + wm * 64 + mi * 16 + g;
            int col = col0 + wn * 32 + ni * 8 + 2 * tg;
            *(float2*)&Y[(size_t)r * DMODEL + col] = make_float2(c[mi][ni][0], c[mi][ni][1]);
            *(float2*)&Y[(size_t)(r + 8) * DMODEL + col] = make_float2(c[mi][ni][2], c[mi][ni][3]);
        }
}

__global__ __launch_bounds__(256) void gemm_qk(const float* __restrict__ X,
                                               const float* __restrict__ Wq,
                                               const float* __restrict__ Wk,
                                               const float* __restrict__ Xr,
                                               const float* __restrict__ Wr,
                                               float* __restrict__ Q,
                                               float* __restrict__ K) {
    extern __shared__ float qsm[];
    float* Asm = qsm;                  // [2][QK_SS]
    float* Bsm = qsm + 2 * QK_SS;
    const int ntile = blockIdx.x;                 // 0..7 Q cols, 8..15 K cols
    const int m0 = blockIdx.y * 128;
    float* Y = (ntile < 8) ? Q : K;
    const int col0 = (ntile & 7) * 128;

    if (ntile == 0 || ntile == 8) {
        const float* Asrc = X + (size_t)m0 * DMODEL;
        const float* Bsrc = (ntile < 8) ? Wq : Wk;
        qk_body<3>(Asrc, Bsrc, Y, m0, col0, Asm, Bsm);   // head0 columns: fp32-class
    } else {
        const float* Asrc = Xr + (size_t)m0 * DMODEL;
        const float* Bsrc = Wr + (size_t)ntile * 128 * DMODEL;  // Wq rows then Wk rows
        qk_body<1>(Asrc, Bsrc, Y, m0, col0, Asm, Bsm);   // attention-only heads: tf32x1 RNA
    }
}

// ---------------- GEMM bf16 x3, cp.async double-buffered ----------
__global__ __launch_bounds__(256) void gemm_bf3(const unsigned* __restrict__ Ah,
                                                const unsigned* __restrict__ Al,
                                                const unsigned* __restrict__ Bh,
                                                const unsigned* __restrict__ Bl,
                                                float* __restrict__ Y,
                                                int M, int N, int Kp) {
    extern __shared__ unsigned dsm[];
    const int AS = 128 * 20;
    const int tid = threadIdx.x, lane = tid & 31, warp = tid >> 5;
    const int g = lane >> 2, tg = lane & 3;
    const int wm = warp >> 2, wn = warp & 3;
    const int m0 = blockIdx.y * 128, n0 = blockIdx.x * 128;

    const int lr = tid >> 2, lc = (tid & 3) * 4;

    float c[4][4][4] = {};

    {
        unsigned* base = dsm;
#pragma unroll
        for (int t = 0; t < 2; t++) {
            int r = lr + t * 64;
            cpa16(&base[0 * AS + r * 20 + lc], &Ah[(size_t)(m0 + r) * Kp + lc]);
            cpa16(&base[1 * AS + r * 20 + lc], &Al[(size_t)(m0 + r) * Kp + lc]);
            cpa16(&base[2 * AS + r * 20 + lc], &Bh[(size_t)(n0 + r) * Kp + lc]);
            cpa16(&base[3 * AS + r * 20 + lc], &Bl[(size_t)(n0 + r) * Kp + lc]);
        }
        CP_COMMIT();
    }

    const int nIt = Kp / 16;
    for (int it = 0; it < nIt; it++) {
        const int st = it & 1;
        if (it + 1 < nIt) {
            const int k0 = (it + 1) * 16;
            unsigned* base = dsm + (st ^ 1) * 4 * AS;
#pragma unroll
            for (int t = 0; t < 2; t++) {
                int r = lr + t * 64;
                cpa16(&base[0 * AS + r * 20 + lc], &Ah[(size_t)(m0 + r) * Kp + k0 + lc]);
                cpa16(&base[1 * AS + r * 20 + lc], &Al[(size_t)(m0 + r) * Kp + k0 + lc]);
                cpa16(&base[2 * AS + r * 20 + lc], &Bh[(size_t)(n0 + r) * Kp + k0 + lc]);
                cpa16(&base[3 * AS + r * 20 + lc], &Bl[(size_t)(n0 + r) * Kp + k0 + lc]);
            }
            CP_COMMIT();
            CP_WAIT1();
        } else {
            CP_WAIT0();
        }
        __syncthreads();

        unsigned* sAh = dsm + st * 4 * AS;
        unsigned* sAl = sAh + AS;
        unsigned* sBh = sAh + 2 * AS;
        unsigned* sBl = sAh + 3 * AS;
#pragma unroll
        for (int kc = 0; kc < 2; kc++) {
            unsigned bhf[4][2], blf[4][2];
#pragma unroll
            for (int ni = 0; ni < 4; ni++) {
                int nb = (wn * 32 + ni * 8 + g) * 20 + kc * 8 + tg;
                bhf[ni][0] = sBh[nb];
                bhf[ni][1] = sBh[nb + 4];
                blf[ni][0] = sBl[nb];
                blf[ni][1] = sBl[nb + 4];
            }
#pragma unroll
            for (int mi = 0; mi < 4; mi++) {
                int r1 = (wm * 64 + mi * 16 + g) * 20 + kc * 8 + tg;
                int r2 = r1 + 8 * 20;
                unsigned ah0 = sAh[r1], ah1 = sAh[r2], ah2 = sAh[r1 + 4], ah3 = sAh[r2 + 4];
                unsigned al0 = sAl[r1], al1 = sAl[r2], al2 = sAl[r1 + 4], al3 = sAl[r2 + 4];
#pragma unroll
                for (int ni = 0; ni < 4; ni++) {
                    MMAB(c[mi][ni], ah0, ah1, ah2, ah3, bhf[ni][0], bhf[ni][1]);
                    MMAB(c[mi][ni], ah0, ah1, ah2, ah3, blf[ni][0], blf[ni][1]);
                    MMAB(c[mi][ni], al0, al1, al2, al3, bhf[ni][0], bhf[ni][1]);
                }
            }
        }
        __syncthreads();
    }

#pragma unroll
    for (int mi = 0; mi < 4; mi++)
#pragma unroll
        for (int ni = 0; ni < 4; ni++) {
            int r = m0 + wm * 64 + mi * 16 + g;
            int col = n0 + wn * 32 + ni * 8 + 2 * tg;
            *(float2*)&Y[(size_t)r * N + col] = make_float2(c[mi][ni][0], c[mi][ni][1]);
            *(float2*)&Y[(size_t)(r + 8) * N + col] = make_float2(c[mi][ni][2], c[mi][ni][3]);
        }
}

// ---------------- row LayerNorm (in place) + scaled tf32-truncated copy ----------------
__global__ __launch_bounds__(256) void ln_rows_t(float* __restrict__ Y,
                                                 const float* __restrict__ g,
                                                 const float* __restrict__ b,
                                                 unsigned* __restrict__ T,
                                                 float scale) {
    const int row = blockIdx.x;
    float* y = Y + (size_t)row * DMODEL;
    unsigned* t = T + (size_t)row * DMODEL;
    __shared__ float red[256];

    float s = 0.f;
    for (int i = threadIdx.x; i < DMODEL; i += 256) s += y[i];
    red[threadIdx.x] = s;
    __syncthreads();
    for (int o = 128; o > 0; o >>= 1) {
        if (threadIdx.x < o) red[threadIdx.x] += red[threadIdx.x + o];
        __syncthreads();
    }
    const float mu = red[0] * (1.0f / DMODEL);
    __syncthreads();

    float v = 0.f;
    for (int i = threadIdx.x; i < DMODEL; i += 256) {
        float d = y[i] - mu;
        v += d * d;
    }
    red[threadIdx.x] = v;
    __syncthreads();
    for (int o = 128; o > 0; o >>= 1) {
        if (threadIdx.x < o) red[threadIdx.x] += red[threadIdx.x + o];
        __syncthreads();
    }
    const float rstd = rsqrtf(red[0] * (1.0f / DMODEL) + 1e-5f);
    __syncthreads();

    for (int i = threadIdx.x; i < DMODEL; i += 256) {
        float val = (y[i] - mu) * rstd * g[i] + b[i];
        y[i] = val;
        t[i] = f2t(val * scale);
    }
}

// ---------------- V transpose + bf16 split ----------------
__global__ __launch_bounds__(256) void vt_split() {
    __shared__ float tile[64][68];
    const int b = blockIdx.z, h = blockIdx.y, n0 = blockIdx.x * 64;
    const int tid = threadIdx.x;
#pragma unroll
    for (int t = 0; t < 4; t++) {
        int idx = tid + t * 256;
        int r = idx >> 4, c4 = (idx & 15) * 4;
        *(float4*)&tile[r][c4] =
            *(const float4*)&g_V[(size_t)(b * SEQL + n0 + r) * DMODEL + h * DHEAD + c4];
    }
    __syncthreads();
#pragma unroll
    for (int t = 0; t < 8; t++) {
        int idx = tid + t * 256;
        int d = idx >> 5, j = idx & 31;
        unsigned hh, ll;
        bsplit(tile[2 * j][d], tile[2 * j + 1][d], hh, ll);
        size_t off = ((size_t)((b * NHEADS + h) * DHEAD + d)) * (SEQL / 2) + (n0 >> 1) + j;
        g_Vth[off] = hh;
        g_Vtl[off] = ll;
    }
}

// ---------------- head-0 scores via tf32 x3 (upper-tri early exit) ----------------
__global__ __launch_bounds__(256) void head0_tc() {
    const int tid = threadIdx.x, lane = tid & 31, warp = tid >> 5;
    const int g = lane >> 2, tg = lane & 3;
    const int wm = warp >> 2, wn = warp & 3;
    const int bb = blockIdx.z;
    const int r0 = blockIdx.y * 128, mm0 = blockIdx.x * 128;

    if (mm0 >= r0 + 128) {
        const float2 z = make_float2(0.f, 0.f);
#pragma unroll
        for (int mi = 0; mi < 4; mi++)
#pragma unroll
            for (int ni = 0; ni < 4; ni++) {
                int r1 = r0 + wm * 64 + mi * 16 + g;
                int m = mm0 + wn * 32 + ni * 8 + 2 * tg;
                *(float2*)&g_F[(size_t)(bb * SEQL + r1) * SEQL + m] = z;
                *(float2*)&g_F[(size_t)(bb * SEQL + r1 + 8) * SEQL + m] = z;
            }
        return;
    }

    __shared__ float As[128][36];
    __shared__ float Bs[128][36];
    const float* Aq = g_Q + (size_t)(bb * SEQL + r0) * DMODEL;
    const float* Bk = g_K + (size_t)(bb * SEQL + mm0) * DMODEL;
    const int lrow = tid >> 3, lcol = (tid & 7) * 4;

    float c[4][4][4] = {};

    for (int k0 = 0; k0 < 64; k0 += 32) {
#pragma unroll
        for (int it = 0; it < 4; it++) {
            int r = lrow + it * 32;
            *(float4*)&As[r][lcol] = *(const float4*)&Aq[(size_t)r * DMODEL + k0 + lcol];
            *(float4*)&Bs[r][lcol] = *(const float4*)&Bk[(size_t)r * DMODEL + k0 + lcol];
        }
        __syncthreads();
#pragma unroll
        for (int kc = 0; kc < 4; kc++) {
            unsigned bh[4][2], bl[4][2];
#pragma unroll
            for (int ni = 0; ni < 4; ni++) {
                int nb = wn * 32 + ni * 8;
                float b0 = Bs[nb + g][kc * 8 + tg];
                float b1 = Bs[nb + g][kc * 8 + tg + 4];
                bh[ni][0] = f2t(b0);
                bh[ni][1] = f2t(b1);
                bl[ni][0] = f2t(b0 - __uint_as_float(bh[ni][0]));
                bl[ni][1] = f2t(b1 - __uint_as_float(bh[ni][1]));
            }
#pragma unroll
            for (int mi = 0; mi < 4; mi++) {
                int rm = wm * 64 + mi * 16;
                float a0 = As[rm + g][kc * 8 + tg];
                float a1 = As[rm + g + 8][kc * 8 + tg];
                float a2 = As[rm + g][kc * 8 + tg + 4];
                float a3 = As[rm + g + 8][kc * 8 + tg + 4];
                unsigned ah0 = f2t(a0), ah1 = f2t(a1), ah2 = f2t(a2), ah3 = f2t(a3);
                unsigned al0 = f2t(a0 - __uint_as_float(ah0));
                unsigned al1 = f2t(a1 - __uint_as_float(ah1));
                unsigned al2 = f2t(a2 - __uint_as_float(ah2));
                unsigned al3 = f2t(a3 - __uint_as_float(ah3));
#pragma unroll
                for (int ni = 0; ni < 4; ni++) {
                    MMA(c[mi][ni], ah0, ah1, ah2, ah3, bh[ni][0], bh[ni][1]);
                    MMA(c[mi][ni], ah0, ah1, ah2, ah3, bl[ni][0], bl[ni][1]);
                    MMA(c[mi][ni], al0, al1, al2, al3, bh[ni][0], bh[ni][1]);
                }
            }
        }
        __syncthreads();
    }

#pragma unroll
    for (int mi = 0; mi < 4; mi++)
#pragma unroll
        for (int ni = 0; ni < 4; ni++) {
            int r1 = r0 + wm * 64 + mi * 16 + g;
            int r2 = r1 + 8;
            int m = mm0 + wn * 32 + ni * 8 + 2 * tg;
            float v0 = c[mi][ni][0] * 0.125f;
            float v1 = c[mi][ni][1] * 0.125f;
            float v2 = c[mi][ni][2] * 0.125f;
            float v3 = c[mi][ni][3] * 0.125f;
            v0 = (m >= 1 && m < r1) ? fmaxf(v0, 0.f) : 0.f;
            v1 = (m + 1 < r1) ? fmaxf(v1, 0.f) : 0.f;
            v2 = (m >= 1 && m < r2) ? fmaxf(v2, 0.f) : 0.f;
            v3 = (m + 1 < r2) ? fmaxf(v3, 0.f) : 0.f;
            *(float2*)&g_F[(size_t)(bb * SEQL + r1) * SEQL + m] = make_float2(v0, v1);
            *(float2*)&g_F[(size_t)(bb * SEQL + r2) * SEQL + m] = make_float2(v2, v3);
        }
}

// ---------------- 3-pass exclusive column scan ----------------
__global__ __launch_bounds__(256) void seg_sum() {
    const int m = blockIdx.x * 256 + threadIdx.x;
    const int seg = blockIdx.y, b = blockIdx.z;
    const float* base = g_F + (size_t)(b * SEQL + seg * SEGROWS) * SEQL + m;
    float s = 0.f;
#pragma unroll 4
    for (int r = 0; r < SEGROWS; r++) s += base[(size_t)r * SEQL];
    g_P[(size_t)(b * NSEG + seg) * SEQL + m] = s;
}

__global__ __launch_bounds__(256) void seg_scan() {
    const int m = blockIdx.x * 256 + threadIdx.x;
    const int b = blockIdx.y;
    float acc = 0.f;
#pragma unroll
    for (int s = 0; s < NSEG; s++) {
        size_t idx = (size_t)(b * NSEG + s) * SEQL + m;
        float v = g_P[idx];
        g_P[idx] = acc;
        acc += v;
    }
}

__global__ __launch_bounds__(256) void final_scan() {
    const int m = blockIdx.x * 256 + threadIdx.x;
    const int seg = blockIdx.y, b = blockIdx.z;
    float acc = g_P[(size_t)(b * NSEG + seg) * SEQL + m];
    float* base = g_F + (size_t)(b * SEQL + seg * SEGROWS) * SEQL + m;
#pragma unroll 4
    for (int r = 0; r < SEGROWS; r++) {
        float c = base[(size_t)r * SEQL];
        base[(size_t)r * SEQL] = acc;
        acc += c;
    }
}

// ---------------- flash attention (Round-9 proven shape): BM=64, 128 threads ----------
#define ATTN_KSZ  (64 * 68)
#define ATTN_VSZ  (64 * 36)
#define ATTN_VHOFF (2 * ATTN_KSZ)
#define ATTN_VLOFF (2 * ATTN_KSZ + 2 * ATTN_VSZ)
#define ATTN_SMEM  ((2 * ATTN_KSZ + 4 * ATTN_VSZ) * 4)

__global__ __launch_bounds__(128) void attn_bf() {
    extern __shared__ unsigned sm[];
    const int b = blockIdx.z, h = blockIdx.y;
    const int qt = (int)gridDim.x - 1 - (int)blockIdx.x;
    const int q0 = qt * 64;
    const int tid = threadIdx.x, lane = tid & 31, w = tid >> 5;
    const int g = lane >> 2, tg = lane & 3;

    unsigned qa[8][4];
    const size_t qr1 = (size_t)(b * SEQL + q0 + w * 16 + g) * DMODEL + h * DHEAD;
    const size_t qr2 = qr1 + 8 * DMODEL;
#pragma unroll
    for (int kc = 0; kc < 8; kc++) {
        qa[kc][0] = g_Qt[qr1 + kc * 8 + tg];
        qa[kc][1] = g_Qt[qr2 + kc * 8 + tg];
        qa[kc][2] = g_Qt[qr1 + kc * 8 + tg + 4];
        qa[kc][3] = g_Qt[qr2 + kc * 8 + tg + 4];
    }

    float o[8][4] = {};
    float qm0 = -1e30f, qm1 = -1e30f, lsum0 = 0.f, lsum1 = 0.f;

    {
        const size_t kbase = (size_t)(b * SEQL) * DMODEL + h * DHEAD;
        const size_t vbase = (size_t)((b * NHEADS + h) * DHEAD) * (SEQL / 2);
#pragma unroll
        for (int t = 0; t < 8; t++) {
            int idx = tid + t * 128;
            int r = idx >> 4, c4 = (idx & 15) * 4;
            cpa16(&sm[r * 68 + c4], &g_Kt[kbase + (size_t)r * DMODEL + c4]);
        }
#pragma unroll
        for (int t = 0; t < 4; t++) {
            int idx = tid + t * 128;
            int r = idx >> 3, c4 = (idx & 7) * 4;
            cpa16(&sm[ATTN_VHOFF + r * 36 + c4], &g_Vth[vbase + (size_t)r * (SEQL / 2) + c4]);
            cpa16(&sm[ATTN_VLOFF + r * 36 + c4], &g_Vtl[vbase + (size_t)r * (SEQL / 2) + c4]);
        }
        CP_COMMIT();
    }

    for (int kt = 0; kt <= qt; kt++) {
        const int buf = kt & 1;
        const int m0 = kt * 64;
        if (kt < qt) {
            const int m0n = m0 + 64;
            const int nb = buf ^ 1;
            const size_t kbase = (size_t)(b * SEQL + m0n) * DMODEL + h * DHEAD;
            const size_t vbase = (size_t)((b * NHEADS + h) * DHEAD) * (SEQL / 2) + (m0n >> 1);
#pragma unroll
            for (int t = 0; t < 8; t++) {
                int idx = tid + t * 128;
                int r = idx >> 4, c4 = (idx & 15) * 4;
                cpa16(&sm[nb * ATTN_KSZ + r * 68 + c4], &g_Kt[kbase + (size_t)r * DMODEL + c4]);
            }
#pragma unroll
            for (int t = 0; t < 4; t++) {
                int idx = tid + t * 128;
                int r = idx >> 3, c4 = (idx & 7) * 4;
                cpa16(&sm[ATTN_VHOFF + nb * ATTN_VSZ + r * 36 + c4],
                      &g_Vth[vbase + (size_t)r * (SEQL / 2) + c4]);
                cpa16(&sm[ATTN_VLOFF + nb * ATTN_VSZ + r * 36 + c4],
                      &g_Vtl[vbase + (size_t)r * (SEQL / 2) + c4]);
            }
            CP_COMMIT();
            CP_WAIT1();
        } else {
            CP_WAIT0();
        }
        __syncthreads();

        const unsigned* sKt = sm + buf * ATTN_KSZ;
        const unsigned* sVh = sm + ATTN_VHOFF + buf * ATTN_VSZ;
        const unsigned* sVl = sm + ATTN_VLOFF + buf * ATTN_VSZ;

        float sc[8][4] = {};
#pragma unroll
        for (int kc = 0; kc < 8; kc++) {
#pragma unroll
            for (int ni = 0; ni < 8; ni++) {
                unsigned b0 = sKt[(ni * 8 + g) * 68 + kc * 8 + tg];
                unsigned b1 = sKt[(ni * 8 + g) * 68 + kc * 8 + tg + 4];
                MMA(sc[ni], qa[kc][0], qa[kc][1], qa[kc][2], qa[kc][3], b0, b1);
            }
        }

        const bool diag = (kt == qt);
        const int lr1 = w * 16 + g, lr2 = lr1 + 8;
        const size_t frow1 = (size_t)(b * SEQL + q0 + lr1) * SEQL + m0;
        const size_t frow2 = (size_t)(b * SEQL + q0 + lr2) * SEQL + m0;
        float mx0 = -1e30f, mx1 = -1e30f;
#pragma unroll
        for (int ni = 0; ni < 8; ni++) {
            int cl = ni * 8 + 2 * tg;
            float2 f1 = *(const float2*)&g_F[frow1 + cl];
            float2 f2 = *(const float2*)&g_F[frow2 + cl];
            float v0 = sc[ni][0] - f1.x;
            float v1 = sc[ni][1] - f1.y;
            float v2 = sc[ni][2] - f2.x;
            float v3 = sc[ni][3] - f2.y;
            if (diag) {
                if (cl > lr1) v0 = -1e30f;
                if (cl + 1 > lr1) v1 = -1e30f;
                if (cl > lr2) v2 = -1e30f;
                if (cl + 1 > lr2) v3 = -1e30f;
            }
            sc[ni][0] = v0; sc[ni][1] = v1; sc[ni][2] = v2; sc[ni][3] = v3;
            mx0 = fmaxf(mx0, fmaxf(v0, v1));
            mx1 = fmaxf(mx1, fmaxf(v2, v3));
        }
        mx0 = fmaxf(mx0, __shfl_xor_sync(0xffffffffu, mx0, 1));
        mx0 = fmaxf(mx0, __shfl_xor_sync(0xffffffffu, mx0, 2));
        mx1 = fmaxf(mx1, __shfl_xor_sync(0xffffffffu, mx1, 1));
        mx1 = fmaxf(mx1, __shfl_xor_sync(0xffffffffu, mx1, 2));
        const float nm0 = fmaxf(qm0, mx0), nm1 = fmaxf(qm1, mx1);
        const float s0 = __expf(qm0 - nm0), s1 = __expf(qm1 - nm1);
        float ps0 = 0.f, ps1 = 0.f;
#pragma unroll
        for (int ni = 0; ni < 8; ni++) {
            float e0 = __expf(sc[ni][0] - nm0);
            float e1 = __expf(sc[ni][1] - nm0);
            float e2 = __expf(sc[ni][2] - nm1);
            float e3 = __expf(sc[ni][3] - nm1);
            sc[ni][0] = e0; sc[ni][1] = e1; sc[ni][2] = e2; sc[ni][3] = e3;
            ps0 += e0 + e1;
            ps1 += e2 + e3;
            o[ni][0] *= s0; o[ni][1] *= s0; o[ni][2] *= s1; o[ni][3] *= s1;
        }
        ps0 += __shfl_xor_sync(0xffffffffu, ps0, 1);
        ps0 += __shfl_xor_sync(0xffffffffu, ps0, 2);
        ps1 += __shfl_xor_sync(0xffffffffu, ps1, 1);
        ps1 += __shfl_xor_sync(0xffffffffu, ps1, 2);
        lsum0 = lsum0 * s0 + ps0;
        lsum1 = lsum1 * s1 + ps1;
        qm0 = nm0; qm1 = nm1;

#pragma unroll
        for (int kc2 = 0; kc2 < 4; kc2++) {
            unsigned ph0, pl0, ph1, pl1, ph2, pl2, ph3, pl3;
            bsplit(sc[kc2 * 2][0], sc[kc2 * 2][1], ph0, pl0);
            bsplit(sc[kc2 * 2][2], sc[kc2 * 2][3], ph1, pl1);
            bsplit(sc[kc2 * 2 + 1][0], sc[kc2 * 2 + 1][1], ph2, pl2);
            bsplit(sc[kc2 * 2 + 1][2], sc[kc2 * 2 + 1][3], ph3, pl3);
#pragma unroll
            for (int ni = 0; ni < 8; ni++) {
                int vb = (ni * 8 + g) * 36 + kc2 * 8 + tg;
                unsigned vh0 = sVh[vb], vh1 = sVh[vb + 4];
                unsigned vl0 = sVl[vb], vl1 = sVl[vb + 4];
                MMAB(o[ni], ph0, ph1, ph2, ph3, vh0, vh1);
                MMAB(o[ni], ph0, ph1, ph2, ph3, vl0, vl1);
                MMAB(o[ni], pl0, pl1, pl2, pl3, vh0, vh1);
            }
        }
        __syncthreads();
    }

    const float i0 = 1.0f / lsum0, i1 = 1.0f / lsum1;
    const size_t or1 = (size_t)(b * SEQL + q0 + w * 16 + g) * KP + h * 32;
    const size_t or2 = or1 + 8 * KP;
#pragma unroll
    for (int ni = 0; ni < 8; ni++) {
        unsigned hh, ll;
        bsplit(o[ni][0] * i0, o[ni][1] * i0, hh, ll);
        g_Oh[or1 + ni * 4 + tg] = hh;
        g_Ol[or1 + ni * 4 + tg] = ll;
        bsplit(o[ni][2] * i1, o[ni][3] * i1, hh, ll);
        g_Oh[or2 + ni * 4 + tg] = hh;
        g_Ol[or2 + ni * 4 + tg] = ll;
    }
}

// ---------------- launch ----------------
extern "C" void kernel_launch(void* const* d_in, const int* in_sizes, int n_in,
                              void* d_out, int out_size) {
    const float* X  = (const float*)d_in[0];
    const float* Wq = (const float*)d_in[1];
    const float* Wk = (const float*)d_in[2];
    const float* Wv = (const float*)d_in[3];
    const float* Wo = (const float*)d_in[4];
    const float* gq = (const float*)d_in[5];
    const float* bq = (const float*)d_in[6];
    const float* gk = (const float*)d_in[7];
    const float* bk = (const float*)d_in[8];
    float* out = (float*)d_out;

    float *pQ, *pK, *pV, *pXr, *pWr;
    unsigned *pQt, *pKt, *pXh, *pXl, *pWvh, *pWvl, *pWoh, *pWol, *pOh, *pOl;
    cudaGetSymbolAddress((void**)&pQ, g_Q);
    cudaGetSymbolAddress((void**)&pK, g_K);
    cudaGetSymbolAddress((void**)&pV, g_V);
    cudaGetSymbolAddress((void**)&pXr, g_Xr);
    cudaGetSymbolAddress((void**)&pWr, g_Wr);
    cudaGetSymbolAddress((void**)&pQt, g_Qt);
    cudaGetSymbolAddress((void**)&pKt, g_Kt);
    cudaGetSymbolAddress((void**)&pXh, g_Xh);
    cudaGetSymbolAddress((void**)&pXl, g_Xl);
    cudaGetSymbolAddress((void**)&pWvh, g_Wvh);
    cudaGetSymbolAddress((void**)&pWvl, g_Wvl);
    cudaGetSymbolAddress((void**)&pWoh, g_Woh);
    cudaGetSymbolAddress((void**)&pWol, g_Wol);
    cudaGetSymbolAddress((void**)&pOh, g_Oh);
    cudaGetSymbolAddress((void**)&pOl, g_Ol);

    const int NW = DMODEL * DMODEL;
    const int GEMM_SMEM = 2 * 4 * 128 * 20 * 4;   // 81920 bytes
    cudaFuncSetAttribute(gemm_bf3, cudaFuncAttributeMaxDynamicSharedMemorySize, GEMM_SMEM);
    cudaFuncSetAttribute(gemm_qk, cudaFuncAttributeMaxDynamicSharedMemorySize, QK_SMEM);
    cudaFuncSetAttribute(attn_bf, cudaFuncAttributeMaxDynamicSharedMemorySize, ATTN_SMEM);

    // operand pre-passes (X rounding fused into its split)
    split_pairs_r<<<(MR * KP + 255) / 256, 256>>>(X, pXh, pXl, (float2*)pXr, MR * KP);
    split_pairs<<<(NW / 2 + 255) / 256, 256>>>(Wv, pWvh, pWvl, NW / 2);
    split_pairs<<<(NW / 2 + 255) / 256, 256>>>(Wo, pWoh, pWol, NW / 2);
    round_t<<<(NW / 4 + 255) / 256, 256>>>(Wq, pWr, NW / 4);
    round_t<<<(NW / 4 + 255) / 256, 256>>>(Wk, pWr + (size_t)NW, NW / 4);

    // fused Q,K projection (mixed tf32 split, RNA, BK=32 2-stage) + V projection (bf16x3)
    gemm_qk<<<dim3(16, MR / 128), 256, QK_SMEM>>>(X, Wq, Wk, pXr, pWr, pQ, pK);
    gemm_bf3<<<dim3(DMODEL / 128, MR / 128), 256, GEMM_SMEM>>>(pXh, pXl, pWvh, pWvl, pV,
                                                               MR, DMODEL, KP);

    ln_rows_t<<<MR, 256>>>(pQ, gq, bq, pQt, 0.125f);   // Qt pre-scaled for attn logits
    ln_rows_t<<<MR, 256>>>(pK, gk, bk, pKt, 1.0f);
    vt_split<<<dim3(SEQL / 64, NHEADS, BATCH), 256>>>();

    head0_tc<<<dim3(SEQL / 128, SEQL / 128, BATCH), 256>>>();
    seg_sum<<<dim3(SEQL / 256, NSEG, BATCH), 256>>>();
    seg_scan<<<dim3(SEQL / 256, BATCH), 256>>>();
    final_scan<<<dim3(SEQL / 256, NSEG, BATCH), 256>>>();

    attn_bf<<<dim3(SEQL / 64, NHEADS, BATCH), 128, ATTN_SMEM>>>();

    gemm_bf3<<<dim3(DMODEL / 128, MR / 128), 256, GEMM_SMEM>>>(pOh, pOl, pWoh, pWol, out,
                                                               MR, DMODEL, KP);
}

// round 12
// speedup vs baseline: 1.0986x; 1.0372x over previous
#include <cuda_runtime.h>
#include <cuda_bf16.h>
#include <math.h>

#define SEQL   2048
#define BATCH  2
#define DMODEL 1024
#define NHEADS 16
#define DHEAD  64
#define MR     (BATCH * SEQL)   // 4096 rows
#define NSEG   16
#define SEGROWS (SEQL / NSEG)   // 128
#define KP     (DMODEL / 2)     // 512 bf16-pair columns

// ---------------- scratch ----------------
__device__ float    g_Q[(size_t)MR * DMODEL];
__device__ float    g_K[(size_t)MR * DMODEL];
__device__ float    g_V[(size_t)MR * DMODEL];
__device__ float    g_Xr[(size_t)MR * DMODEL];         // tf32-rounded X (x1 path)
__device__ float    g_Wr[(size_t)2 * DMODEL * DMODEL]; // Wq then Wk, rounded
__device__ unsigned g_Qt[(size_t)MR * DMODEL];         // tf32 hi bits, PRE-SCALED by 0.125
__device__ unsigned g_Kt[(size_t)MR * DMODEL];
__device__ unsigned g_Xh[(size_t)MR * KP];
__device__ unsigned g_Xl[(size_t)MR * KP];
__device__ unsigned g_Wvh[(size_t)DMODEL * KP];
__device__ unsigned g_Wvl[(size_t)DMODEL * KP];
__device__ unsigned g_Woh[(size_t)DMODEL * KP];
__device__ unsigned g_Wol[(size_t)DMODEL * KP];
__device__ unsigned g_Vth[(size_t)BATCH * NHEADS * DHEAD * (SEQL / 2)];
__device__ unsigned g_Vtl[(size_t)BATCH * NHEADS * DHEAD * (SEQL / 2)];
__device__ unsigned g_Oh[(size_t)MR * KP];
__device__ unsigned g_Ol[(size_t)MR * KP];
__device__ float    g_F[(size_t)BATCH * SEQL * SEQL];
__device__ float    g_P[(size_t)BATCH * NSEG * SEQL];

// ---------------- helpers ----------------
__device__ __forceinline__ unsigned f2t(float x) {
    unsigned r;
    asm("cvt.rna.tf32.f32 %0, %1;" : "=r"(r) : "f"(x));
    return r;
}

__device__ __forceinline__ void bsplit(float x0, float x1, unsigned& h, unsigned& l) {
    asm("cvt.rn.bf16x2.f32 %0, %1, %2;" : "=r"(h) : "f"(x1), "f"(x0));
    __nv_bfloat162 hb = *reinterpret_cast<__nv_bfloat162*>(&h);
    float2 hf = __bfloat1622float2(hb);
    float r0 = x0 - hf.x, r1 = x1 - hf.y;
    asm("cvt.rn.bf16x2.f32 %0, %1, %2;" : "=r"(l) : "f"(r1), "f"(r0));
}

__device__ __forceinline__ void cpa16(void* smem, const void* gmem) {
    unsigned s = (unsigned)__cvta_generic_to_shared(smem);
    asm volatile("cp.async.cg.shared.global [%0], [%1], 16;" :: "r"(s), "l"(gmem));
}
#define CP_COMMIT() asm volatile("cp.async.commit_group;")
#define CP_WAIT1()  asm volatile("cp.async.wait_group 1;")
#define CP_WAIT0()  asm volatile("cp.async.wait_group 0;")

#define MMA(C, A0, A1, A2, A3, B0, B1)                                         \
    asm volatile(                                                              \
        "mma.sync.aligned.m16n8k8.row.col.f32.tf32.tf32.f32 "                  \
        "{%0,%1,%2,%3},{%4,%5,%6,%7},{%8,%9},{%0,%1,%2,%3};"                   \
        : "+f"((C)[0]), "+f"((C)[1]), "+f"((C)[2]), "+f"((C)[3])               \
        : "r"(A0), "r"(A1), "r"(A2), "r"(A3), "r"(B0), "r"(B1))

#define MMAB(C, A0, A1, A2, A3, B0, B1)                                        \
    asm volatile(                                                              \
        "mma.sync.aligned.m16n8k16.row.col.f32.bf16.bf16.f32 "                 \
        "{%0,%1,%2,%3},{%4,%5,%6,%7},{%8,%9},{%0,%1,%2,%3};"                   \
        : "+f"((C)[0]), "+f"((C)[1]), "+f"((C)[2]), "+f"((C)[3])               \
        : "r"(A0), "r"(A1), "r"(A2), "r"(A3), "r"(B0), "r"(B1))

// ---------------- mega prepass: all operand splits/rounds in ONE launch --------------
// seg 0: X -> Xh/Xl + Xr (2M pairs)
// seg 1: Wv -> Wvh/Wvl (512K pairs)      seg 2: Wo -> Woh/Wol (512K pairs)
// seg 3: Wq -> Wr[0:1M) (512K pairs)     seg 4: Wk -> Wr[1M:2M) (512K pairs)
#define PRE_N0 (MR * KP)
#define PRE_N1 (DMODEL * KP)
#define PRE_TOT (PRE_N0 + 4 * PRE_N1)

__global__ __launch_bounds__(256) void prepass(const float* __restrict__ X,
                                               const float* __restrict__ Wv,
                                               const float* __restrict__ Wo,
                                               const float* __restrict__ Wq,
                                               const float* __restrict__ Wk) {
    int i = blockIdx.x * 256 + threadIdx.x;
    if (i < PRE_N0) {
        float2 v = ((const float2*)X)[i];
        unsigned hh, ll;
        bsplit(v.x, v.y, hh, ll);
        g_Xh[i] = hh;
        g_Xl[i] = ll;
        float2 o;
        o.x = __uint_as_float(f2t(v.x));
        o.y = __uint_as_float(f2t(v.y));
        ((float2*)g_Xr)[i] = o;
        return;
    }
    i -= PRE_N0;
    if (i < PRE_N1) {
        float2 v = ((const float2*)Wv)[i];
        unsigned hh, ll;
        bsplit(v.x, v.y, hh, ll);
        g_Wvh[i] = hh;
        g_Wvl[i] = ll;
        return;
    }
    i -= PRE_N1;
    if (i < PRE_N1) {
        float2 v = ((const float2*)Wo)[i];
        unsigned hh, ll;
        bsplit(v.x, v.y, hh, ll);
        g_Woh[i] = hh;
        g_Wol[i] = ll;
        return;
    }
    i -= PRE_N1;
    if (i < PRE_N1) {
        float2 v = ((const float2*)Wq)[i];
        float2 o;
        o.x = __uint_as_float(f2t(v.x));
        o.y = __uint_as_float(f2t(v.y));
        ((float2*)g_Wr)[i] = o;
        return;
    }
    i -= PRE_N1;
    if (i < PRE_N1) {
        float2 v = ((const float2*)Wk)[i];
        float2 o;
        o.x = __uint_as_float(f2t(v.x));
        o.y = __uint_as_float(f2t(v.y));
        ((float2*)(g_Wr + (size_t)DMODEL * DMODEL))[i] = o;
    }
}

// ---------------- qk tile body (BK=32, 2-stage, mixed split) ----------------
#define QK_SS   (128 * 36)                   // floats per array per stage

template <int SPLIT>
__device__ __forceinline__ void qk_body(const float* __restrict__ Asrc,
                                        const float* __restrict__ Bsrc,
                                        float* __restrict__ Y,
                                        int m0, int col0,
                                        float* __restrict__ Asm,
                                        float* __restrict__ Bsm) {
    const int tid = threadIdx.x, lane = tid & 31, warp = tid >> 5;
    const int g = lane >> 2, tg = lane & 3;
    const int wm = warp >> 2, wn = warp & 3;

    float c[4][4][4] = {};

#define QK_LOAD(stage, k0)                                                     \
    do {                                                                       \
        float* As_ = Asm + (stage) * QK_SS;                                    \
        float* Bs_ = Bsm + (stage) * QK_SS;                                    \
        _Pragma("unroll")                                                      \
        for (int t = 0; t < 4; t++) {                                          \
            int idx = tid + t * 256;                                           \
            int r = idx >> 3, c4 = (idx & 7) * 4;                              \
            cpa16(&As_[r * 36 + c4], &Asrc[(size_t)r * DMODEL + (k0) + c4]);   \
            cpa16(&Bs_[r * 36 + c4], &Bsrc[(size_t)r * DMODEL + (k0) + c4]);   \
        }                                                                      \
    } while (0)

    QK_LOAD(0, 0);
    CP_COMMIT();

    const int nIt = DMODEL / 32;
    for (int it = 0; it < nIt; it++) {
        const int st = it & 1;
        if (it + 1 < nIt) {
            QK_LOAD(st ^ 1, (it + 1) * 32);
            CP_COMMIT();
            CP_WAIT1();
        } else {
            CP_WAIT0();
        }
        __syncthreads();

        const float* As_ = Asm + st * QK_SS;
        const float* Bs_ = Bsm + st * QK_SS;
#pragma unroll
        for (int kc = 0; kc < 4; kc++) {
            unsigned bh[4][2], bl[4][2];
#pragma unroll
            for (int ni = 0; ni < 4; ni++) {
                int nb = (wn * 32 + ni * 8 + g) * 36 + kc * 8 + tg;
                float b0 = Bs_[nb];
                float b1 = Bs_[nb + 4];
                if (SPLIT == 3) {
                    bh[ni][0] = f2t(b0);
                    bh[ni][1] = f2t(b1);
                    bl[ni][0] = f2t(b0 - __uint_as_float(bh[ni][0]));
                    bl[ni][1] = f2t(b1 - __uint_as_float(bh[ni][1]));
                } else {
                    bh[ni][0] = __float_as_uint(b0);
                    bh[ni][1] = __float_as_uint(b1);
                }
            }
#pragma unroll
            for (int mi = 0; mi < 4; mi++) {
                int r1 = (wm * 64 + mi * 16 + g) * 36 + kc * 8 + tg;
                int r2 = r1 + 8 * 36;
                float a0 = As_[r1];
                float a1 = As_[r2];
                float a2 = As_[r1 + 4];
                float a3 = As_[r2 + 4];
                unsigned ah0, ah1, ah2, ah3;
                unsigned al0 = 0, al1 = 0, al2 = 0, al3 = 0;
                if (SPLIT == 3) {
                    ah0 = f2t(a0); ah1 = f2t(a1); ah2 = f2t(a2); ah3 = f2t(a3);
                    al0 = f2t(a0 - __uint_as_float(ah0));
                    al1 = f2t(a1 - __uint_as_float(ah1));
                    al2 = f2t(a2 - __uint_as_float(ah2));
                    al3 = f2t(a3 - __uint_as_float(ah3));
                } else {
                    ah0 = __float_as_uint(a0); ah1 = __float_as_uint(a1);
                    ah2 = __float_as_uint(a2); ah3 = __float_as_uint(a3);
                }
#pragma unroll
                for (int ni = 0; ni < 4; ni++) {
                    MMA(c[mi][ni], ah0, ah1, ah2, ah3, bh[ni][0], bh[ni][1]);
                    if (SPLIT == 3) {
                        MMA(c[mi][ni], ah0, ah1, ah2, ah3, bl[ni][0], bl[ni][1]);
                        MMA(c[mi][ni], al0, al1, al2, al3, bh[ni][0], bh[ni][1]);
                    }
                }
            }
        }
        __syncthreads();
    }
#undef QK_LOAD

#pragma unroll
    for (int mi = 0; mi < 4; mi++)
#pragma unroll
        for (int ni = 0; ni < 4; ni++) {
            int r = m0 + wm * 64 + mi * 16 + g;
            int col = col0 + wn * 32 + ni * 8 + 2 * tg;
            *(float2*)&Y[(size_t)r * DMODEL + col] = make_float2(c[mi][ni][0], c[mi][ni][1]);
            *(float2*)&Y[(size_t)(r + 8) * DMODEL + col] = make_float2(c[mi][ni][2], c[mi][ni][3]);
        }
}

// ---------------- bf16x3 tile body (BK=16 pairs, 2-stage) ----------------
__device__ __forceinline__ void bf3_body(const unsigned* __restrict__ Ah,
                                         const unsigned* __restrict__ Al,
                                         const unsigned* __restrict__ Bh,
                                         const unsigned* __restrict__ Bl,
                                         float* __restrict__ Y,
                                         int m0, int n0, int N, int Kp,
                                         unsigned* __restrict__ dsm) {
    const int AS = 128 * 20;
    const int tid = threadIdx.x, lane = tid & 31, warp = tid >> 5;
    const int g = lane >> 2, tg = lane & 3;
    const int wm = warp >> 2, wn = warp & 3;
    const int lr = tid >> 2, lc = (tid & 3) * 4;

    float c[4][4][4] = {};

    {
        unsigned* base = dsm;
#pragma unroll
        for (int t = 0; t < 2; t++) {
            int r = lr + t * 64;
            cpa16(&base[0 * AS + r * 20 + lc], &Ah[(size_t)(m0 + r) * Kp + lc]);
            cpa16(&base[1 * AS + r * 20 + lc], &Al[(size_t)(m0 + r) * Kp + lc]);
            cpa16(&base[2 * AS + r * 20 + lc], &Bh[(size_t)(n0 + r) * Kp + lc]);
            cpa16(&base[3 * AS + r * 20 + lc], &Bl[(size_t)(n0 + r) * Kp + lc]);
        }
        CP_COMMIT();
    }

    const int nIt = Kp / 16;
    for (int it = 0; it < nIt; it++) {
        const int st = it & 1;
        if (it + 1 < nIt) {
            const int k0 = (it + 1) * 16;
            unsigned* base = dsm + (st ^ 1) * 4 * AS;
#pragma unroll
            for (int t = 0; t < 2; t++) {
                int r = lr + t * 64;
                cpa16(&base[0 * AS + r * 20 + lc], &Ah[(size_t)(m0 + r) * Kp + k0 + lc]);
                cpa16(&base[1 * AS + r * 20 + lc], &Al[(size_t)(m0 + r) * Kp + k0 + lc]);
                cpa16(&base[2 * AS + r * 20 + lc], &Bh[(size_t)(n0 + r) * Kp + k0 + lc]);
                cpa16(&base[3 * AS + r * 20 + lc], &Bl[(size_t)(n0 + r) * Kp + k0 + lc]);
            }
            CP_COMMIT();
            CP_WAIT1();
        } else {
            CP_WAIT0();
        }
        __syncthreads();

        unsigned* sAh = dsm + st * 4 * AS;
        unsigned* sAl = sAh + AS;
        unsigned* sBh = sAh + 2 * AS;
        unsigned* sBl = sAh + 3 * AS;
#pragma unroll
        for (int kc = 0; kc < 2; kc++) {
            unsigned bhf[4][2], blf[4][2];
#pragma unroll
            for (int ni = 0; ni < 4; ni++) {
                int nb = (wn * 32 + ni * 8 + g) * 20 + kc * 8 + tg;
                bhf[ni][0] = sBh[nb];
                bhf[ni][1] = sBh[nb + 4];
                blf[ni][0] = sBl[nb];
                blf[ni][1] = sBl[nb + 4];
            }
#pragma unroll
            for (int mi = 0; mi < 4; mi++) {
                int r1 = (wm * 64 + mi * 16 + g) * 20 + kc * 8 + tg;
                int r2 = r1 + 8 * 20;
                unsigned ah0 = sAh[r1], ah1 = sAh[r2], ah2 = sAh[r1 + 4], ah3 = sAh[r2 + 4];
                unsigned al0 = sAl[r1], al1 = sAl[r2], al2 = sAl[r1 + 4], al3 = sAl[r2 + 4];
#pragma unroll
                for (int ni = 0; ni < 4; ni++) {
                    MMAB(c[mi][ni], ah0, ah1, ah2, ah3, bhf[ni][0], bhf[ni][1]);
                    MMAB(c[mi][ni], ah0, ah1, ah2, ah3, blf[ni][0], blf[ni][1]);
                    MMAB(c[mi][ni], al0, al1, al2, al3, bhf[ni][0], bhf[ni][1]);
                }
            }
        }
        __syncthreads();
    }

#pragma unroll
    for (int mi = 0; mi < 4; mi++)
#pragma unroll
        for (int ni = 0; ni < 4; ni++) {
            int r = m0 + wm * 64 + mi * 16 + g;
            int col = n0 + wn * 32 + ni * 8 + 2 * tg;
            *(float2*)&Y[(size_t)r * N + col] = make_float2(c[mi][ni][0], c[mi][ni][1]);
            *(float2*)&Y[(size_t)(r + 8) * N + col] = make_float2(c[mi][ni][2], c[mi][ni][3]);
        }
}

// ---------------- fused projections: QK (mixed tf32) + V (bf16x3) in one grid --------
#define PROJ_SMEM (2 * 4 * 128 * 20 * 4)   // 81920 B (max of bf3 80K, qk 72K)

__global__ __launch_bounds__(256) void proj_fused(const float* __restrict__ X,
                                                  const float* __restrict__ Wq,
                                                  const float* __restrict__ Wk,
                                                  const float* __restrict__ Xr,
                                                  const float* __restrict__ Wr,
                                                  float* __restrict__ Q,
                                                  float* __restrict__ K,
                                                  float* __restrict__ V) {
    extern __shared__ float fsm[];
    const int xt = blockIdx.x;          // 0..15 qk tiles, 16..23 V tiles
    const int m0 = blockIdx.y * 128;

    if (xt < 16) {
        float* Asm = fsm;               // [2][QK_SS]
        float* Bsm = fsm + 2 * QK_SS;
        float* Y = (xt < 8) ? Q : K;
        const int col0 = (xt & 7) * 128;
        if (xt == 0 || xt == 8) {
            const float* Asrc = X + (size_t)m0 * DMODEL;
            const float* Bsrc = (xt < 8) ? Wq : Wk;
            qk_body<3>(Asrc, Bsrc, Y, m0, col0, Asm, Bsm);
        } else {
            const float* Asrc = Xr + (size_t)m0 * DMODEL;
            const float* Bsrc = Wr + (size_t)xt * 128 * DMODEL;
            qk_body<1>(Asrc, Bsrc, Y, m0, col0, Asm, Bsm);
        }
    } else {
        bf3_body(g_Xh, g_Xl, g_Wvh, g_Wvl, V, m0, (xt - 16) * 128, DMODEL, KP,
                 (unsigned*)fsm);
    }
}

// ---------------- standalone bf16x3 GEMM (output projection) ----------
__global__ __launch_bounds__(256) void gemm_bf3(const unsigned* __restrict__ Ah,
                                                const unsigned* __restrict__ Al,
                                                const unsigned* __restrict__ Bh,
                                                const unsigned* __restrict__ Bl,
                                                float* __restrict__ Y,
                                                int M, int N, int Kp) {
    extern __shared__ unsigned dsm[];
    bf3_body(Ah, Al, Bh, Bl, Y, blockIdx.y * 128, blockIdx.x * 128, N, Kp, dsm);
}

// ---------------- row LayerNorm + scaled tf32 copy ----------------
__global__ __launch_bounds__(256) void ln_rows_t(float* __restrict__ Y,
                                                 const float* __restrict__ g,
                                                 const float* __restrict__ b,
                                                 unsigned* __restrict__ T,
                                                 float scale) {
    const int row = blockIdx.x;
    float* y = Y + (size_t)row * DMODEL;
    unsigned* t = T + (size_t)row * DMODEL;
    __shared__ float red[256];

    float s = 0.f;
    for (int i = threadIdx.x; i < DMODEL; i += 256) s += y[i];
    red[threadIdx.x] = s;
    __syncthreads();
    for (int o = 128; o > 0; o >>= 1) {
        if (threadIdx.x < o) red[threadIdx.x] += red[threadIdx.x + o];
        __syncthreads();
    }
    const float mu = red[0] * (1.0f / DMODEL);
    __syncthreads();

    float v = 0.f;
    for (int i = threadIdx.x; i < DMODEL; i += 256) {
        float d = y[i] - mu;
        v += d * d;
    }
    red[threadIdx.x] = v;
    __syncthreads();
    for (int o = 128; o > 0; o >>= 1) {
        if (threadIdx.x < o) red[threadIdx.x] += red[threadIdx.x + o];
        __syncthreads();
    }
    const float rstd = rsqrtf(red[0] * (1.0f / DMODEL) + 1e-5f);
    __syncthreads();

    for (int i = threadIdx.x; i < DMODEL; i += 256) {
        float val = (y[i] - mu) * rstd * g[i] + b[i];
        y[i] = val;
        t[i] = f2t(val * scale);
    }
}

// ---------------- V transpose + bf16 split ----------------
__global__ __launch_bounds__(256) void vt_split() {
    __shared__ float tile[64][68];
    const int b = blockIdx.z, h = blockIdx.y, n0 = blockIdx.x * 64;
    const int tid = threadIdx.x;
#pragma unroll
    for (int t = 0; t < 4; t++) {
        int idx = tid + t * 256;
        int r = idx >> 4, c4 = (idx & 15) * 4;
        *(float4*)&tile[r][c4] =
            *(const float4*)&g_V[(size_t)(b * SEQL + n0 + r) * DMODEL + h * DHEAD + c4];
    }
    __syncthreads();
#pragma unroll
    for (int t = 0; t < 8; t++) {
        int idx = tid + t * 256;
        int d = idx >> 5, j = idx & 31;
        unsigned hh, ll;
        bsplit(tile[2 * j][d], tile[2 * j + 1][d], hh, ll);
        size_t off = ((size_t)((b * NHEADS + h) * DHEAD + d)) * (SEQL / 2) + (n0 >> 1) + j;
        g_Vth[off] = hh;
        g_Vtl[off] = ll;
    }
}

// ---------------- head-0 scores via tf32 x3 (upper-tri early exit) ----------------
__global__ __launch_bounds__(256) void head0_tc() {
    const int tid = threadIdx.x, lane = tid & 31, warp = tid >> 5;
    const int g = lane >> 2, tg = lane & 3;
    const int wm = warp >> 2, wn = warp & 3;
    const int bb = blockIdx.z;
    const int r0 = blockIdx.y * 128, mm0 = blockIdx.x * 128;

    if (mm0 >= r0 + 128) {
        const float2 z = make_float2(0.f, 0.f);
#pragma unroll
        for (int mi = 0; mi < 4; mi++)
#pragma unroll
            for (int ni = 0; ni < 4; ni++) {
                int r1 = r0 + wm * 64 + mi * 16 + g;
                int m = mm0 + wn * 32 + ni * 8 + 2 * tg;
                *(float2*)&g_F[(size_t)(bb * SEQL + r1) * SEQL + m] = z;
                *(float2*)&g_F[(size_t)(bb * SEQL + r1 + 8) * SEQL + m] = z;
            }
        return;
    }

    __shared__ float As[128][36];
    __shared__ float Bs[128][36];
    const float* Aq = g_Q + (size_t)(bb * SEQL + r0) * DMODEL;
    const float* Bk = g_K + (size_t)(bb * SEQL + mm0) * DMODEL;
    const int lrow = tid >> 3, lcol = (tid & 7) * 4;

    float c[4][4][4] = {};

    for (int k0 = 0; k0 < 64; k0 += 32) {
#pragma unroll
        for (int it = 0; it < 4; it++) {
            int r = lrow + it * 32;
            *(float4*)&As[r][lcol] = *(const float4*)&Aq[(size_t)r * DMODEL + k0 + lcol];
            *(float4*)&Bs[r][lcol] = *(const float4*)&Bk[(size_t)r * DMODEL + k0 + lcol];
        }
        __syncthreads();
#pragma unroll
        for (int kc = 0; kc < 4; kc++) {
            unsigned bh[4][2], bl[4][2];
#pragma unroll
            for (int ni = 0; ni < 4; ni++) {
                int nb = wn * 32 + ni * 8;
                float b0 = Bs[nb + g][kc * 8 + tg];
                float b1 = Bs[nb + g][kc * 8 + tg + 4];
                bh[ni][0] = f2t(b0);
                bh[ni][1] = f2t(b1);
                bl[ni][0] = f2t(b0 - __uint_as_float(bh[ni][0]));
                bl[ni][1] = f2t(b1 - __uint_as_float(bh[ni][1]));
            }
#pragma unroll
            for (int mi = 0; mi < 4; mi++) {
                int rm = wm * 64 + mi * 16;
                float a0 = As[rm + g][kc * 8 + tg];
                float a1 = As[rm + g + 8][kc * 8 + tg];
                float a2 = As[rm + g][kc * 8 + tg + 4];
                float a3 = As[rm + g + 8][kc * 8 + tg + 4];
                unsigned ah0 = f2t(a0), ah1 = f2t(a1), ah2 = f2t(a2), ah3 = f2t(a3);
                unsigned al0 = f2t(a0 - __uint_as_float(ah0));
                unsigned al1 = f2t(a1 - __uint_as_float(ah1));
                unsigned al2 = f2t(a2 - __uint_as_float(ah2));
                unsigned al3 = f2t(a3 - __uint_as_float(ah3));
#pragma unroll
                for (int ni = 0; ni < 4; ni++) {
                    MMA(c[mi][ni], ah0, ah1, ah2, ah3, bh[ni][0], bh[ni][1]);
                    MMA(c[mi][ni], ah0, ah1, ah2, ah3, bl[ni][0], bl[ni][1]);
                    MMA(c[mi][ni], al0, al1, al2, al3, bh[ni][0], bh[ni][1]);
                }
            }
        }
        __syncthreads();
    }

#pragma unroll
    for (int mi = 0; mi < 4; mi++)
#pragma unroll
        for (int ni = 0; ni < 4; ni++) {
            int r1 = r0 + wm * 64 + mi * 16 + g;
            int r2 = r1 + 8;
            int m = mm0 + wn * 32 + ni * 8 + 2 * tg;
            float v0 = c[mi][ni][0] * 0.125f;
            float v1 = c[mi][ni][1] * 0.125f;
            float v2 = c[mi][ni][2] * 0.125f;
            float v3 = c[mi][ni][3] * 0.125f;
            v0 = (m >= 1 && m < r1) ? fmaxf(v0, 0.f) : 0.f;
            v1 = (m + 1 < r1) ? fmaxf(v1, 0.f) : 0.f;
            v2 = (m >= 1 && m < r2) ? fmaxf(v2, 0.f) : 0.f;
            v3 = (m + 1 < r2) ? fmaxf(v3, 0.f) : 0.f;
            *(float2*)&g_F[(size_t)(bb * SEQL + r1) * SEQL + m] = make_float2(v0, v1);
            *(float2*)&g_F[(size_t)(bb * SEQL + r2) * SEQL + m] = make_float2(v2, v3);
        }
}

// ---------------- 3-pass exclusive column scan ----------------
__global__ __launch_bounds__(256) void seg_sum() {
    const int m = blockIdx.x * 256 + threadIdx.x;
    const int seg = blockIdx.y, b = blockIdx.z;
    const float* base = g_F + (size_t)(b * SEQL + seg * SEGROWS) * SEQL + m;
    float s = 0.f;
#pragma unroll 4
    for (int r = 0; r < SEGROWS; r++) s += base[(size_t)r * SEQL];
    g_P[(size_t)(b * NSEG + seg) * SEQL + m] = s;
}

__global__ __launch_bounds__(256) void seg_scan() {
    const int m = blockIdx.x * 256 + threadIdx.x;
    const int b = blockIdx.y;
    float acc = 0.f;
#pragma unroll
    for (int s = 0; s < NSEG; s++) {
        size_t idx = (size_t)(b * NSEG + s) * SEQL + m;
        float v = g_P[idx];
        g_P[idx] = acc;
        acc += v;
    }
}

__global__ __launch_bounds__(256) void final_scan() {
    const int m = blockIdx.x * 256 + threadIdx.x;
    const int seg = blockIdx.y, b = blockIdx.z;
    float acc = g_P[(size_t)(b * NSEG + seg) * SEQL + m];
    float* base = g_F + (size_t)(b * SEQL + seg * SEGROWS) * SEQL + m;
#pragma unroll 4
    for (int r = 0; r < SEGROWS; r++) {
        float c = base[(size_t)r * SEQL];
        base[(size_t)r * SEQL] = acc;
        acc += c;
    }
}

// ---------------- flash attention: BM=64, 128 threads, cp.async K/V ----------
#define ATTN_KSZ  (64 * 68)
#define ATTN_VSZ  (64 * 36)
#define ATTN_VHOFF (2 * ATTN_KSZ)
#define ATTN_VLOFF (2 * ATTN_KSZ + 2 * ATTN_VSZ)
#define ATTN_SMEM  ((2 * ATTN_KSZ + 4 * ATTN_VSZ) * 4)

__global__ __launch_bounds__(128) void attn_bf() {
    extern __shared__ unsigned sm[];
    const int b = blockIdx.z, h = blockIdx.y;
    const int qt = (int)gridDim.x - 1 - (int)blockIdx.x;
    const int q0 = qt * 64;
    const int tid = threadIdx.x, lane = tid & 31, w = tid >> 5;
    const int g = lane >> 2, tg = lane & 3;

    unsigned qa[8][4];
    const size_t qr1 = (size_t)(b * SEQL + q0 + w * 16 + g) * DMODEL + h * DHEAD;
    const size_t qr2 = qr1 + 8 * DMODEL;
#pragma unroll
    for (int kc = 0; kc < 8; kc++) {
        qa[kc][0] = g_Qt[qr1 + kc * 8 + tg];
        qa[kc][1] = g_Qt[qr2 + kc * 8 + tg];
        qa[kc][2] = g_Qt[qr1 + kc * 8 + tg + 4];
        qa[kc][3] = g_Qt[qr2 + kc * 8 + tg + 4];
    }

    float o[8][4] = {};
    float qm0 = -1e30f, qm1 = -1e30f, lsum0 = 0.f, lsum1 = 0.f;

    {
        const size_t kbase = (size_t)(b * SEQL) * DMODEL + h * DHEAD;
        const size_t vbase = (size_t)((b * NHEADS + h) * DHEAD) * (SEQL / 2);
#pragma unroll
        for (int t = 0; t < 8; t++) {
            int idx = tid + t * 128;
            int r = idx >> 4, c4 = (idx & 15) * 4;
            cpa16(&sm[r * 68 + c4], &g_Kt[kbase + (size_t)r * DMODEL + c4]);
        }
#pragma unroll
        for (int t = 0; t < 4; t++) {
            int idx = tid + t * 128;
            int r = idx >> 3, c4 = (idx & 7) * 4;
            cpa16(&sm[ATTN_VHOFF + r * 36 + c4], &g_Vth[vbase + (size_t)r * (SEQL / 2) + c4]);
            cpa16(&sm[ATTN_VLOFF + r * 36 + c4], &g_Vtl[vbase + (size_t)r * (SEQL / 2) + c4]);
        }
        CP_COMMIT();
    }

    for (int kt = 0; kt <= qt; kt++) {
        const int buf = kt & 1;
        const int m0 = kt * 64;
        if (kt < qt) {
            const int m0n = m0 + 64;
            const int nb = buf ^ 1;
            const size_t kbase = (size_t)(b * SEQL + m0n) * DMODEL + h * DHEAD;
            const size_t vbase = (size_t)((b * NHEADS + h) * DHEAD) * (SEQL / 2) + (m0n >> 1);
#pragma unroll
            for (int t = 0; t < 8; t++) {
                int idx = tid + t * 128;
                int r = idx >> 4, c4 = (idx & 15) * 4;
                cpa16(&sm[nb * ATTN_KSZ + r * 68 + c4], &g_Kt[kbase + (size_t)r * DMODEL + c4]);
            }
#pragma unroll
            for (int t = 0; t < 4; t++) {
                int idx = tid + t * 128;
                int r = idx >> 3, c4 = (idx & 7) * 4;
                cpa16(&sm[ATTN_VHOFF + nb * ATTN_VSZ + r * 36 + c4],
                      &g_Vth[vbase + (size_t)r * (SEQL / 2) + c4]);
                cpa16(&sm[ATTN_VLOFF + nb * ATTN_VSZ + r * 36 + c4],
                      &g_Vtl[vbase + (size_t)r * (SEQL / 2) + c4]);
            }
            CP_COMMIT();
            CP_WAIT1();
        } else {
            CP_WAIT0();
        }
        __syncthreads();

        const unsigned* sKt = sm + buf * ATTN_KSZ;
        const unsigned* sVh = sm + ATTN_VHOFF + buf * ATTN_VSZ;
        const unsigned* sVl = sm + ATTN_VLOFF + buf * ATTN_VSZ;

        float sc[8][4] = {};
#pragma unroll
        for (int kc = 0; kc < 8; kc++) {
#pragma unroll
            for (int ni = 0; ni < 8; ni++) {
                unsigned b0 = sKt[(ni * 8 + g) * 68 + kc * 8 + tg];
                unsigned b1 = sKt[(ni * 8 + g) * 68 + kc * 8 + tg + 4];
                MMA(sc[ni], qa[kc][0], qa[kc][1], qa[kc][2], qa[kc][3], b0, b1);
            }
        }

        const bool diag = (kt == qt);
        const int lr1 = w * 16 + g, lr2 = lr1 + 8;
        const size_t frow1 = (size_t)(b * SEQL + q0 + lr1) * SEQL + m0;
        const size_t frow2 = (size_t)(b * SEQL + q0 + lr2) * SEQL + m0;
        float mx0 = -1e30f, mx1 = -1e30f;
#pragma unroll
        for (int ni = 0; ni < 8; ni++) {
            int cl = ni * 8 + 2 * tg;
            float2 f1 = *(const float2*)&g_F[frow1 + cl];
            float2 f2 = *(const float2*)&g_F[frow2 + cl];
            float v0 = sc[ni][0] - f1.x;
            float v1 = sc[ni][1] - f1.y;
            float v2 = sc[ni][2] - f2.x;
            float v3 = sc[ni][3] - f2.y;
            if (diag) {
                if (cl > lr1) v0 = -1e30f;
                if (cl + 1 > lr1) v1 = -1e30f;
                if (cl > lr2) v2 = -1e30f;
                if (cl + 1 > lr2) v3 = -1e30f;
            }
            sc[ni][0] = v0; sc[ni][1] = v1; sc[ni][2] = v2; sc[ni][3] = v3;
            mx0 = fmaxf(mx0, fmaxf(v0, v1));
            mx1 = fmaxf(mx1, fmaxf(v2, v3));
        }
        mx0 = fmaxf(mx0, __shfl_xor_sync(0xffffffffu, mx0, 1));
        mx0 = fmaxf(mx0, __shfl_xor_sync(0xffffffffu, mx0, 2));
        mx1 = fmaxf(mx1, __shfl_xor_sync(0xffffffffu, mx1, 1));
        mx1 = fmaxf(mx1, __shfl_xor_sync(0xffffffffu, mx1, 2));
        const float nm0 = fmaxf(qm0, mx0), nm1 = fmaxf(qm1, mx1);
        const float s0 = __expf(qm0 - nm0), s1 = __expf(qm1 - nm1);
        float ps0 = 0.f, ps1 = 0.f;
#pragma unroll
        for (int ni = 0; ni < 8; ni++) {
            float e0 = __expf(sc[ni][0] - nm0);
            float e1 = __expf(sc[ni][1] - nm0);
            float e2 = __expf(sc[ni][2] - nm1);
            float e3 = __expf(sc[ni][3] - nm1);
            sc[ni][0] = e0; sc[ni][1] = e1; sc[ni][2] = e2; sc[ni][3] = e3;
            ps0 += e0 + e1;
            ps1 += e2 + e3;
            o[ni][0] *= s0; o[ni][1] *= s0; o[ni][2] *= s1; o[ni][3] *= s1;
        }
        ps0 += __shfl_xor_sync(0xffffffffu, ps0, 1);
        ps0 += __shfl_xor_sync(0xffffffffu, ps0, 2);
        ps1 += __shfl_xor_sync(0xffffffffu, ps1, 1);
        ps1 += __shfl_xor_sync(0xffffffffu, ps1, 2);
        lsum0 = lsum0 * s0 + ps0;
        lsum1 = lsum1 * s1 + ps1;
        qm0 = nm0; qm1 = nm1;

#pragma unroll
        for (int kc2 = 0; kc2 < 4; kc2++) {
            unsigned ph0, pl0, ph1, pl1, ph2, pl2, ph3, pl3;
            bsplit(sc[kc2 * 2][0], sc[kc2 * 2][1], ph0, pl0);
            bsplit(sc[kc2 * 2][2], sc[kc2 * 2][3], ph1, pl1);
            bsplit(sc[kc2 * 2 + 1][0], sc[kc2 * 2 + 1][1], ph2, pl2);
            bsplit(sc[kc2 * 2 + 1][2], sc[kc2 * 2 + 1][3], ph3, pl3);
#pragma unroll
            for (int ni = 0; ni < 8; ni++) {
                int vb = (ni * 8 + g) * 36 + kc2 * 8 + tg;
                unsigned vh0 = sVh[vb], vh1 = sVh[vb + 4];
                unsigned vl0 = sVl[vb], vl1 = sVl[vb + 4];
                MMAB(o[ni], ph0, ph1, ph2, ph3, vh0, vh1);
                MMAB(o[ni], ph0, ph1, ph2, ph3, vl0, vl1);
                MMAB(o[ni], pl0, pl1, pl2, pl3, vh0, vh1);
            }
        }
        __syncthreads();
    }

    const float i0 = 1.0f / lsum0, i1 = 1.0f / lsum1;
    const size_t or1 = (size_t)(b * SEQL + q0 + w * 16 + g) * KP + h * 32;
    const size_t or2 = or1 + 8 * KP;
#pragma unroll
    for (int ni = 0; ni < 8; ni++) {
        unsigned hh, ll;
        bsplit(o[ni][0] * i0, o[ni][1] * i0, hh, ll);
        g_Oh[or1 + ni * 4 + tg] = hh;
        g_Ol[or1 + ni * 4 + tg] = ll;
        bsplit(o[ni][2] * i1, o[ni][3] * i1, hh, ll);
        g_Oh[or2 + ni * 4 + tg] = hh;
        g_Ol[or2 + ni * 4 + tg] = ll;
    }
}

// ---------------- launch ----------------
extern "C" void kernel_launch(void* const* d_in, const int* in_sizes, int n_in,
                              void* d_out, int out_size) {
    const float* X  = (const float*)d_in[0];
    const float* Wq = (const float*)d_in[1];
    const float* Wk = (const float*)d_in[2];
    const float* Wv = (const float*)d_in[3];
    const float* Wo = (const float*)d_in[4];
    const float* gq = (const float*)d_in[5];
    const float* bq = (const float*)d_in[6];
    const float* gk = (const float*)d_in[7];
    const float* bk = (const float*)d_in[8];
    float* out = (float*)d_out;

    float *pQ, *pK, *pV, *pXr, *pWr;
    unsigned *pQt, *pKt, *pWoh, *pWol, *pOh, *pOl;
    cudaGetSymbolAddress((void**)&pQ, g_Q);
    cudaGetSymbolAddress((void**)&pK, g_K);
    cudaGetSymbolAddress((void**)&pV, g_V);
    cudaGetSymbolAddress((void**)&pXr, g_Xr);
    cudaGetSymbolAddress((void**)&pWr, g_Wr);
    cudaGetSymbolAddress((void**)&pQt, g_Qt);
    cudaGetSymbolAddress((void**)&pKt, g_Kt);
    cudaGetSymbolAddress((void**)&pWoh, g_Woh);
    cudaGetSymbolAddress((void**)&pWol, g_Wol);
    cudaGetSymbolAddress((void**)&pOh, g_Oh);
    cudaGetSymbolAddress((void**)&pOl, g_Ol);

    cudaFuncSetAttribute(proj_fused, cudaFuncAttributeMaxDynamicSharedMemorySize, PROJ_SMEM);
    cudaFuncSetAttribute(gemm_bf3, cudaFuncAttributeMaxDynamicSharedMemorySize, PROJ_SMEM);
    cudaFuncSetAttribute(attn_bf, cudaFuncAttributeMaxDynamicSharedMemorySize, ATTN_SMEM);

    // all operand prepasses in one launch
    prepass<<<(PRE_TOT + 255) / 256, 256>>>(X, Wv, Wo, Wq, Wk);

    // fused QK (mixed tf32) + V (bf16x3) projections in one grid
    proj_fused<<<dim3(24, MR / 128), 256, PROJ_SMEM>>>(X, Wq, Wk, pXr, pWr, pQ, pK, pV);

    ln_rows_t<<<MR, 256>>>(pQ, gq, bq, pQt, 0.125f);
    ln_rows_t<<<MR, 256>>>(pK, gk, bk, pKt, 1.0f);
    vt_split<<<dim3(SEQL / 64, NHEADS, BATCH), 256>>>();

    head0_tc<<<dim3(SEQL / 128, SEQL / 128, BATCH), 256>>>();
    seg_sum<<<dim3(SEQL / 256, NSEG, BATCH), 256>>>();
    seg_scan<<<dim3(SEQL / 256, BATCH), 256>>>();
    final_scan<<<dim3(SEQL / 256, NSEG, BATCH), 256>>>();

    attn_bf<<<dim3(SEQL / 64, NHEADS, BATCH), 128, ATTN_SMEM>>>();

    gemm_bf3<<<dim3(DMODEL / 128, MR / 128), 256, PROJ_SMEM>>>(pOh, pOl, pWoh, pWol, out,
                                                               MR, DMODEL, KP);
}